// round 1
// baseline (speedup 1.0000x reference)
#include <cuda_runtime.h>
#include <cstdint>

// Problem dims (fixed by the reference)
#define S_ 2048
#define B_ 2
#define E_ 1024
#define H_ 16
#define DH_ 64
#define M_ (S_ * B_)        // 4096 rows for the projections
#define SCALING_ 0.125f     // DH^-0.5

// ---------------------------------------------------------------------------
// Scratch (allocation-free rule: __device__ globals)
// ---------------------------------------------------------------------------
__device__ float g_q[(size_t)M_ * E_];
__device__ float g_k[(size_t)M_ * E_];
__device__ float g_v[(size_t)M_ * E_];
__device__ float g_ctx[(size_t)M_ * E_];

// ---------------------------------------------------------------------------
// SGEMM (NT): C[m][n] = alpha * ( sum_k A[m][k] * W[n][k] + bias[n] )
// A: [M x K] row-major, W: [N x K] row-major. BM=BN=128, BK=8, 256 threads,
// 8x8 register fragment per thread.
// ---------------------------------------------------------------------------
__global__ __launch_bounds__(256)
void sgemm_nt_bias(const float* __restrict__ A, const float* __restrict__ W,
                   const float* __restrict__ bias, float* __restrict__ C,
                   int M, int N, int K, float alpha)
{
    __shared__ __align__(16) float As[8][132];
    __shared__ __align__(16) float Bs[8][132];

    const int bx = blockIdx.x;      // N tile
    const int by = blockIdx.y;      // M tile
    const int tid = threadIdx.x;
    const int tx = tid & 15;        // 0..15 (N)
    const int ty = tid >> 4;        // 0..15 (M)

    const int lrow = tid >> 1;          // 0..127
    const int lk   = (tid & 1) << 2;    // 0 or 4

    const float* Ap = A + (size_t)(by * 128 + lrow) * K + lk;
    const float* Wp = W + (size_t)(bx * 128 + lrow) * K + lk;

    float acc[8][8];
#pragma unroll
    for (int i = 0; i < 8; ++i)
#pragma unroll
        for (int j = 0; j < 8; ++j) acc[i][j] = 0.0f;

    for (int k0 = 0; k0 < K; k0 += 8) {
        float4 av = *(const float4*)(Ap + k0);
        float4 wv = *(const float4*)(Wp + k0);
        As[lk + 0][lrow] = av.x; As[lk + 1][lrow] = av.y;
        As[lk + 2][lrow] = av.z; As[lk + 3][lrow] = av.w;
        Bs[lk + 0][lrow] = wv.x; Bs[lk + 1][lrow] = wv.y;
        Bs[lk + 2][lrow] = wv.z; Bs[lk + 3][lrow] = wv.w;
        __syncthreads();

#pragma unroll
        for (int kk = 0; kk < 8; ++kk) {
            float a[8], b[8];
            *(float4*)(a)     = *(const float4*)(&As[kk][ty * 8]);
            *(float4*)(a + 4) = *(const float4*)(&As[kk][ty * 8 + 4]);
            *(float4*)(b)     = *(const float4*)(&Bs[kk][tx * 8]);
            *(float4*)(b + 4) = *(const float4*)(&Bs[kk][tx * 8 + 4]);
#pragma unroll
            for (int i = 0; i < 8; ++i)
#pragma unroll
                for (int j = 0; j < 8; ++j)
                    acc[i][j] = fmaf(a[i], b[j], acc[i][j]);
        }
        __syncthreads();
    }

    const int row0 = by * 128 + ty * 8;
    const int col0 = bx * 128 + tx * 8;
    float bv[8];
#pragma unroll
    for (int j = 0; j < 8; ++j) bv[j] = bias[col0 + j];
#pragma unroll
    for (int i = 0; i < 8; ++i) {
        float* cp = C + (size_t)(row0 + i) * N + col0;
#pragma unroll
        for (int j = 0; j < 8; ++j)
            cp[j] = alpha * (acc[i][j] + bv[j]);
    }
}

// ---------------------------------------------------------------------------
// Flash attention, fp32. CTA: (q-tile of 128, head, batch). K-tiles of 64.
// 256 threads. Thread (tr = tid>>3, tc = tid&7) owns rows tr*4..tr*4+3 and
// score/output columns {tc + 8*j, j=0..7} (strided -> conflict-free LDS).
// SMEM rows padded to 65 floats.
// ---------------------------------------------------------------------------
#define ATT_BQ 128
#define ATT_TK 64
#define ATT_PAD 65

__global__ __launch_bounds__(256)
void attn_flash(const float* __restrict__ Qb, const float* __restrict__ Kb,
                const float* __restrict__ Vb, float* __restrict__ Ctx)
{
    const int qt = blockIdx.x;   // 0..15
    const int h  = blockIdx.y;   // 0..15
    const int b  = blockIdx.z;   // 0..1

    extern __shared__ float sm[];
    float* Qs = sm;                                   // [128][65]
    float* Ks = Qs + ATT_BQ * ATT_PAD;                // [64][65]
    float* Vs = Ks + ATT_TK * ATT_PAD;                // [64][65]
    float* Ps = Vs + ATT_TK * ATT_PAD;                // [128][65]

    const int tid = threadIdx.x;
    const int tr = tid >> 3;      // 0..31
    const int tc = tid & 7;       // 0..7
    const int r0 = tr * 4;

    const size_t rstride = (size_t)B_ * E_;           // 2048 floats
    const float* qbase = Qb + ((size_t)(qt * ATT_BQ) * B_ + b) * E_ + h * DH_;

    // Load Q tile (coalesced float4)
    for (int i = tid; i < ATT_BQ * 16; i += 256) {
        int r = i >> 4, c = (i & 15) << 2;
        float4 v = *(const float4*)(qbase + (size_t)r * rstride + c);
        float* d = &Qs[r * ATT_PAD + c];
        d[0] = v.x; d[1] = v.y; d[2] = v.z; d[3] = v.w;
    }

    float o[4][8];
    float mr[4], lr[4];
#pragma unroll
    for (int i = 0; i < 4; ++i) {
        mr[i] = -1e30f; lr[i] = 0.0f;
#pragma unroll
        for (int j = 0; j < 8; ++j) o[i][j] = 0.0f;
    }
    __syncthreads();

    for (int kt = 0; kt < S_ / ATT_TK; ++kt) {
        const float* kb = Kb + ((size_t)(kt * ATT_TK) * B_ + b) * E_ + h * DH_;
        const float* vb = Vb + ((size_t)(kt * ATT_TK) * B_ + b) * E_ + h * DH_;
        for (int i = tid; i < ATT_TK * 16; i += 256) {
            int r = i >> 4, c = (i & 15) << 2;
            float4 kv = *(const float4*)(kb + (size_t)r * rstride + c);
            float4 vv = *(const float4*)(vb + (size_t)r * rstride + c);
            float* dk = &Ks[r * ATT_PAD + c];
            dk[0] = kv.x; dk[1] = kv.y; dk[2] = kv.z; dk[3] = kv.w;
            float* dv = &Vs[r * ATT_PAD + c];
            dv[0] = vv.x; dv[1] = vv.y; dv[2] = vv.z; dv[3] = vv.w;
        }
        __syncthreads();

        // S = Q K^T  (thread cols: key index tc + 8*j)
        float s[4][8];
#pragma unroll
        for (int i = 0; i < 4; ++i)
#pragma unroll
            for (int j = 0; j < 8; ++j) s[i][j] = 0.0f;

#pragma unroll 8
        for (int d = 0; d < DH_; ++d) {
            float a0 = Qs[(r0 + 0) * ATT_PAD + d];
            float a1 = Qs[(r0 + 1) * ATT_PAD + d];
            float a2 = Qs[(r0 + 2) * ATT_PAD + d];
            float a3 = Qs[(r0 + 3) * ATT_PAD + d];
            float kf[8];
#pragma unroll
            for (int j = 0; j < 8; ++j)
                kf[j] = Ks[(tc + 8 * j) * ATT_PAD + d];
#pragma unroll
            for (int j = 0; j < 8; ++j) {
                s[0][j] = fmaf(a0, kf[j], s[0][j]);
                s[1][j] = fmaf(a1, kf[j], s[1][j]);
                s[2][j] = fmaf(a2, kf[j], s[2][j]);
                s[3][j] = fmaf(a3, kf[j], s[3][j]);
            }
        }

        // Online softmax update per row (reduce across the 8 tc lanes)
#pragma unroll
        for (int i = 0; i < 4; ++i) {
            float mx = s[i][0];
#pragma unroll
            for (int j = 1; j < 8; ++j) mx = fmaxf(mx, s[i][j]);
            mx = fmaxf(mx, __shfl_xor_sync(0xffffffffu, mx, 1));
            mx = fmaxf(mx, __shfl_xor_sync(0xffffffffu, mx, 2));
            mx = fmaxf(mx, __shfl_xor_sync(0xffffffffu, mx, 4));
            float mnew = fmaxf(mr[i], mx);
            float corr = __expf(mr[i] - mnew);
            float lsum = 0.0f;
#pragma unroll
            for (int j = 0; j < 8; ++j) {
                float p = __expf(s[i][j] - mnew);
                s[i][j] = p;
                lsum += p;
            }
            lsum += __shfl_xor_sync(0xffffffffu, lsum, 1);
            lsum += __shfl_xor_sync(0xffffffffu, lsum, 2);
            lsum += __shfl_xor_sync(0xffffffffu, lsum, 4);
            lr[i] = lr[i] * corr + lsum;
            mr[i] = mnew;
#pragma unroll
            for (int j = 0; j < 8; ++j) {
                o[i][j] *= corr;
                Ps[(r0 + i) * ATT_PAD + tc + 8 * j] = s[i][j];
            }
        }
        __syncthreads();

        // O += P V  (thread output cols: tc + 8*j)
#pragma unroll 8
        for (int k = 0; k < ATT_TK; ++k) {
            float p0 = Ps[(r0 + 0) * ATT_PAD + k];
            float p1 = Ps[(r0 + 1) * ATT_PAD + k];
            float p2 = Ps[(r0 + 2) * ATT_PAD + k];
            float p3 = Ps[(r0 + 3) * ATT_PAD + k];
            float vf[8];
#pragma unroll
            for (int j = 0; j < 8; ++j)
                vf[j] = Vs[k * ATT_PAD + tc + 8 * j];
#pragma unroll
            for (int j = 0; j < 8; ++j) {
                o[0][j] = fmaf(p0, vf[j], o[0][j]);
                o[1][j] = fmaf(p1, vf[j], o[1][j]);
                o[2][j] = fmaf(p2, vf[j], o[2][j]);
                o[3][j] = fmaf(p3, vf[j], o[3][j]);
            }
        }
        __syncthreads();
    }

    // Epilogue: normalize and write ctx[(q*B+b)*E + h*DH + col]
#pragma unroll
    for (int i = 0; i < 4; ++i) {
        float inv = 1.0f / lr[i];
        float* cp = Ctx + ((size_t)(qt * ATT_BQ + r0 + i) * B_ + b) * E_ + h * DH_;
#pragma unroll
        for (int j = 0; j < 8; ++j)
            cp[tc + 8 * j] = o[i][j] * inv;
    }
}

// ---------------------------------------------------------------------------
// Launcher (graph-capturable: kernel launches + attribute/symbol queries only)
// ---------------------------------------------------------------------------
extern "C" void kernel_launch(void* const* d_in, const int* in_sizes, int n_in,
                              void* d_out, int out_size)
{
    const float* query = (const float*)d_in[0];
    const float* wq = (const float*)d_in[1];
    const float* bq = (const float*)d_in[2];
    const float* wk = (const float*)d_in[3];
    const float* bk = (const float*)d_in[4];
    const float* wv = (const float*)d_in[5];
    const float* bv = (const float*)d_in[6];
    const float* wo = (const float*)d_in[7];
    const float* bo = (const float*)d_in[8];
    float* out = (float*)d_out;

    float *qb, *kb, *vb, *cb;
    cudaGetSymbolAddress((void**)&qb, g_q);
    cudaGetSymbolAddress((void**)&kb, g_k);
    cudaGetSymbolAddress((void**)&vb, g_v);
    cudaGetSymbolAddress((void**)&cb, g_ctx);

    dim3 ggrid(E_ / 128, M_ / 128);   // (8, 32)

    sgemm_nt_bias<<<ggrid, 256>>>(query, wq, bq, qb, M_, E_, E_, SCALING_);
    sgemm_nt_bias<<<ggrid, 256>>>(query, wk, bk, kb, M_, E_, E_, 1.0f);
    sgemm_nt_bias<<<ggrid, 256>>>(query, wv, bv, vb, M_, E_, E_, 1.0f);

    size_t smem = (size_t)(ATT_BQ + ATT_TK + ATT_TK + ATT_BQ) * ATT_PAD * sizeof(float);
    cudaFuncSetAttribute(attn_flash, cudaFuncAttributeMaxDynamicSharedMemorySize, (int)smem);
    attn_flash<<<dim3(S_ / ATT_BQ, H_, B_), 256, smem>>>(qb, kb, vb, cb);

    sgemm_nt_bias<<<ggrid, 256>>>(cb, wo, bo, out, M_, E_, E_, 1.0f);
}

// round 3
// speedup vs baseline: 1.6061x; 1.6061x over previous
#include <cuda_runtime.h>
#include <cstdint>

// Problem dims (fixed by the reference)
#define S_ 2048
#define B_ 2
#define E_ 1024
#define H_ 16
#define DH_ 64
#define M_ (S_ * B_)        // 4096 rows for the projections
#define SCALING_ 0.125f     // DH^-0.5

// ---------------------------------------------------------------------------
// Scratch (allocation-free rule: __device__ globals)
// ---------------------------------------------------------------------------
__device__ float g_q[(size_t)M_ * E_];
__device__ float g_k[(size_t)M_ * E_];
__device__ float g_v[(size_t)M_ * E_];
__device__ float g_ctx[(size_t)M_ * E_];

// ---------------------------------------------------------------------------
// Baseline-PTX tensor helpers (work on .target sm_103 — no 'a' features)
// ---------------------------------------------------------------------------
__device__ __forceinline__ uint32_t smem_u32(const void* p) {
    uint32_t a;
    asm("{ .reg .u64 t; cvta.to.shared.u64 t, %1; cvt.u32.u64 %0, t; }"
        : "=r"(a) : "l"(p));
    return a;
}

__device__ __forceinline__ uint32_t cvt_tf32(float x) {
    uint32_t r;
    asm("cvt.rna.tf32.f32 %0, %1;" : "=r"(r) : "f"(x));
    return r;
}

__device__ __forceinline__ void ldsm_x4(uint32_t addr, uint32_t& r0, uint32_t& r1,
                                        uint32_t& r2, uint32_t& r3) {
    asm volatile("ldmatrix.sync.aligned.m8n8.x4.shared.b16 {%0,%1,%2,%3}, [%4];"
                 : "=r"(r0), "=r"(r1), "=r"(r2), "=r"(r3) : "r"(addr));
}

__device__ __forceinline__ void mma_tf32(float* d, const uint32_t* a, const uint32_t* b) {
    asm volatile(
        "mma.sync.aligned.m16n8k8.row.col.f32.tf32.tf32.f32 "
        "{%0,%1,%2,%3}, {%4,%5,%6,%7}, {%8,%9}, {%0,%1,%2,%3};"
        : "+f"(d[0]), "+f"(d[1]), "+f"(d[2]), "+f"(d[3])
        : "r"(a[0]), "r"(a[1]), "r"(a[2]), "r"(a[3]), "r"(b[0]), "r"(b[1]));
}

#define CP_ASYNC16(dst, src) \
    asm volatile("cp.async.cg.shared.global [%0], [%1], 16;" \
                 :: "r"(dst), "l"(src) : "memory")
#define CP_COMMIT() asm volatile("cp.async.commit_group;" ::: "memory")
#define CP_WAIT1()  asm volatile("cp.async.wait_group 1;" ::: "memory")

__device__ __forceinline__ uint32_t sw128(uint32_t off) {
    return off ^ ((off >> 3) & 0x70);
}

// ---------------------------------------------------------------------------
// mma.sync tf32 GEMM (NT): C[m][n] = alpha * (sum_k A[m][k]*W[n][k] + bias[n])
// A: [M x 1024] row-major, W: [N x 1024] row-major (so W is the col-major B).
// CTA 128x128, BK=32, cp.async double buffer. 8 warps = 2(M) x 4(N), each
// warp a 64x32 tile = 4 m-frags x 4 n-frags of m16n8k8.
// ---------------------------------------------------------------------------
#define GK 1024
#define BK 32
#define NCH (GK / BK)            // 32
#define OPBYTES (128 * BK * 4)   // 16 KB per operand per buffer

__global__ __launch_bounds__(256, 2)
void gemm_mma_tf32(const float* __restrict__ A, const float* __restrict__ W,
                   const float* __restrict__ bias, float* __restrict__ C,
                   float alpha)
{
    extern __shared__ __align__(128) char smg[];
    const uint32_t sb = smem_u32(smg);
    // buffers: A0 | B0 | A1 | B1
    const uint32_t aB[2] = { sb, sb + 2 * OPBYTES };
    const uint32_t bB[2] = { sb + OPBYTES, sb + 3 * OPBYTES };

    const int tid = threadIdx.x;
    const int wid = tid >> 5;
    const int lane = tid & 31;
    const int warp_m = wid & 1;        // 0..1 -> m offset *64
    const int warp_n = wid >> 1;       // 0..3 -> n offset *32
    const int bx = blockIdx.x;         // N tile
    const int by = blockIdx.y;         // M tile

    const float* Ap = A + (size_t)(by * 128) * GK;
    const float* Wp = W + (size_t)(bx * 128) * GK;

    // cp.async load mapping: idx = tid + 256*i -> row = idx>>3, chunk16 = idx&7
    const int ldrow = tid >> 3;            // needs idx<1024: i loop adds rows
    const int ldc16 = tid & 7;

    // ldmatrix lane-address components (precomputed)
    const int a_row_base = warp_m * 64 + (lane & 15);          // + mf*16
    const int a_hi = (lane & 16) ? 1 : 0;                       // +16B chunk
    const int b_row_base = warp_n * 32 + (lane & 7) + ((lane & 16) >> 1); // + nfp*16
    const int b_hi = (lane & 8) ? 1 : 0;

    float acc[4][4][4];
#pragma unroll
    for (int i = 0; i < 4; ++i)
#pragma unroll
        for (int j = 0; j < 4; ++j)
#pragma unroll
            for (int r = 0; r < 4; ++r) acc[i][j][r] = 0.0f;

    // issue chunk c into buffer buf
    auto issue = [&](int c, int buf) {
#pragma unroll
        for (int i = 0; i < 4; ++i) {
            int row = ldrow + i * 32;
            uint32_t sw = sw128((uint32_t)(row * 128 + ldc16 * 16));
            const float* ga = Ap + (size_t)row * GK + c * BK + ldc16 * 4;
            const float* gw = Wp + (size_t)row * GK + c * BK + ldc16 * 4;
            CP_ASYNC16(aB[buf] + sw, ga);
            CP_ASYNC16(bB[buf] + sw, gw);
        }
    };

    issue(0, 0); CP_COMMIT();
    issue(1, 1); CP_COMMIT();

    for (int c = 0; c < NCH; ++c) {
        const int buf = c & 1;
        CP_WAIT1();
        __syncthreads();

#pragma unroll
        for (int s = 0; s < 4; ++s) {          // k8 steps within BK=32
            // B fragments: 2 x ldmatrix.x4 -> 4 n-frags of {b0,b1}
            uint32_t bfr[4][2];
#pragma unroll
            for (int nfp = 0; nfp < 2; ++nfp) {
                int row = b_row_base + nfp * 16;
                uint32_t off = (uint32_t)(row * 128 + (s * 2 + b_hi) * 16);
                uint32_t r0, r1, r2, r3;
                ldsm_x4(bB[buf] + sw128(off), r0, r1, r2, r3);
                bfr[2 * nfp + 0][0] = cvt_tf32(__uint_as_float(r0));
                bfr[2 * nfp + 0][1] = cvt_tf32(__uint_as_float(r1));
                bfr[2 * nfp + 1][0] = cvt_tf32(__uint_as_float(r2));
                bfr[2 * nfp + 1][1] = cvt_tf32(__uint_as_float(r3));
            }
#pragma unroll
            for (int mf = 0; mf < 4; ++mf) {
                int row = a_row_base + mf * 16;
                uint32_t off = (uint32_t)(row * 128 + (s * 2 + a_hi) * 16);
                uint32_t afr[4];
                ldsm_x4(aB[buf] + sw128(off), afr[0], afr[1], afr[2], afr[3]);
#pragma unroll
                for (int r = 0; r < 4; ++r) afr[r] = cvt_tf32(__uint_as_float(afr[r]));
#pragma unroll
                for (int nf = 0; nf < 4; ++nf)
                    mma_tf32(acc[mf][nf], afr, bfr[nf]);
            }
        }
        __syncthreads();
        if (c + 2 < NCH) issue(c + 2, buf);
        CP_COMMIT();
    }

    // Epilogue: C layout c0=(row=lane/4, col=2*(lane&3)), c2/c3 at row+8
    const int gq = lane >> 2;
    const int tg = lane & 3;
#pragma unroll
    for (int nf = 0; nf < 4; ++nf) {
        const int col = bx * 128 + warp_n * 32 + nf * 8 + 2 * tg;
        const float bv0 = bias[col], bv1 = bias[col + 1];
#pragma unroll
        for (int mf = 0; mf < 4; ++mf) {
            const int r0 = by * 128 + warp_m * 64 + mf * 16 + gq;
            float2 lo, hi;
            lo.x = alpha * (acc[mf][nf][0] + bv0);
            lo.y = alpha * (acc[mf][nf][1] + bv1);
            hi.x = alpha * (acc[mf][nf][2] + bv0);
            hi.y = alpha * (acc[mf][nf][3] + bv1);
            *(float2*)(C + (size_t)r0 * E_ + col) = lo;
            *(float2*)(C + (size_t)(r0 + 8) * E_ + col) = hi;
        }
    }
}

// ---------------------------------------------------------------------------
// Flash attention, fp32 (unchanged from R1 — passing at rel_err 1e-6)
// ---------------------------------------------------------------------------
#define ATT_BQ 128
#define ATT_TK 64
#define ATT_PAD 65

__global__ __launch_bounds__(256)
void attn_flash(const float* __restrict__ Qb, const float* __restrict__ Kb,
                const float* __restrict__ Vb, float* __restrict__ Ctx)
{
    const int qt = blockIdx.x;
    const int h  = blockIdx.y;
    const int b  = blockIdx.z;

    extern __shared__ float smf[];
    float* Qs = smf;
    float* Ks = Qs + ATT_BQ * ATT_PAD;
    float* Vs = Ks + ATT_TK * ATT_PAD;
    float* Ps = Vs + ATT_TK * ATT_PAD;

    const int tid = threadIdx.x;
    const int tr = tid >> 3;
    const int tc = tid & 7;
    const int r0 = tr * 4;

    const size_t rstride = (size_t)B_ * E_;
    const float* qbase = Qb + ((size_t)(qt * ATT_BQ) * B_ + b) * E_ + h * DH_;

    for (int i = tid; i < ATT_BQ * 16; i += 256) {
        int r = i >> 4, c = (i & 15) << 2;
        float4 v = *(const float4*)(qbase + (size_t)r * rstride + c);
        float* d = &Qs[r * ATT_PAD + c];
        d[0] = v.x; d[1] = v.y; d[2] = v.z; d[3] = v.w;
    }

    float o[4][8];
    float mr[4], lr[4];
#pragma unroll
    for (int i = 0; i < 4; ++i) {
        mr[i] = -1e30f; lr[i] = 0.0f;
#pragma unroll
        for (int j = 0; j < 8; ++j) o[i][j] = 0.0f;
    }
    __syncthreads();

    for (int kt = 0; kt < S_ / ATT_TK; ++kt) {
        const float* kb = Kb + ((size_t)(kt * ATT_TK) * B_ + b) * E_ + h * DH_;
        const float* vb = Vb + ((size_t)(kt * ATT_TK) * B_ + b) * E_ + h * DH_;
        for (int i = tid; i < ATT_TK * 16; i += 256) {
            int r = i >> 4, c = (i & 15) << 2;
            float4 kv = *(const float4*)(kb + (size_t)r * rstride + c);
            float4 vv = *(const float4*)(vb + (size_t)r * rstride + c);
            float* dk = &Ks[r * ATT_PAD + c];
            dk[0] = kv.x; dk[1] = kv.y; dk[2] = kv.z; dk[3] = kv.w;
            float* dv = &Vs[r * ATT_PAD + c];
            dv[0] = vv.x; dv[1] = vv.y; dv[2] = vv.z; dv[3] = vv.w;
        }
        __syncthreads();

        float s[4][8];
#pragma unroll
        for (int i = 0; i < 4; ++i)
#pragma unroll
            for (int j = 0; j < 8; ++j) s[i][j] = 0.0f;

#pragma unroll 8
        for (int d = 0; d < DH_; ++d) {
            float a0 = Qs[(r0 + 0) * ATT_PAD + d];
            float a1 = Qs[(r0 + 1) * ATT_PAD + d];
            float a2 = Qs[(r0 + 2) * ATT_PAD + d];
            float a3 = Qs[(r0 + 3) * ATT_PAD + d];
            float kf[8];
#pragma unroll
            for (int j = 0; j < 8; ++j)
                kf[j] = Ks[(tc + 8 * j) * ATT_PAD + d];
#pragma unroll
            for (int j = 0; j < 8; ++j) {
                s[0][j] = fmaf(a0, kf[j], s[0][j]);
                s[1][j] = fmaf(a1, kf[j], s[1][j]);
                s[2][j] = fmaf(a2, kf[j], s[2][j]);
                s[3][j] = fmaf(a3, kf[j], s[3][j]);
            }
        }

#pragma unroll
        for (int i = 0; i < 4; ++i) {
            float mx = s[i][0];
#pragma unroll
            for (int j = 1; j < 8; ++j) mx = fmaxf(mx, s[i][j]);
            mx = fmaxf(mx, __shfl_xor_sync(0xffffffffu, mx, 1));
            mx = fmaxf(mx, __shfl_xor_sync(0xffffffffu, mx, 2));
            mx = fmaxf(mx, __shfl_xor_sync(0xffffffffu, mx, 4));
            float mnew = fmaxf(mr[i], mx);
            float corr = __expf(mr[i] - mnew);
            float lsum = 0.0f;
#pragma unroll
            for (int j = 0; j < 8; ++j) {
                float p = __expf(s[i][j] - mnew);
                s[i][j] = p;
                lsum += p;
            }
            lsum += __shfl_xor_sync(0xffffffffu, lsum, 1);
            lsum += __shfl_xor_sync(0xffffffffu, lsum, 2);
            lsum += __shfl_xor_sync(0xffffffffu, lsum, 4);
            lr[i] = lr[i] * corr + lsum;
            mr[i] = mnew;
#pragma unroll
            for (int j = 0; j < 8; ++j) {
                o[i][j] *= corr;
                Ps[(r0 + i) * ATT_PAD + tc + 8 * j] = s[i][j];
            }
        }
        __syncthreads();

#pragma unroll 8
        for (int k = 0; k < ATT_TK; ++k) {
            float p0 = Ps[(r0 + 0) * ATT_PAD + k];
            float p1 = Ps[(r0 + 1) * ATT_PAD + k];
            float p2 = Ps[(r0 + 2) * ATT_PAD + k];
            float p3 = Ps[(r0 + 3) * ATT_PAD + k];
            float vf[8];
#pragma unroll
            for (int j = 0; j < 8; ++j)
                vf[j] = Vs[k * ATT_PAD + tc + 8 * j];
#pragma unroll
            for (int j = 0; j < 8; ++j) {
                o[0][j] = fmaf(p0, vf[j], o[0][j]);
                o[1][j] = fmaf(p1, vf[j], o[1][j]);
                o[2][j] = fmaf(p2, vf[j], o[2][j]);
                o[3][j] = fmaf(p3, vf[j], o[3][j]);
            }
        }
        __syncthreads();
    }

#pragma unroll
    for (int i = 0; i < 4; ++i) {
        float inv = 1.0f / lr[i];
        float* cp = Ctx + ((size_t)(qt * ATT_BQ + r0 + i) * B_ + b) * E_ + h * DH_;
#pragma unroll
        for (int j = 0; j < 8; ++j)
            cp[tc + 8 * j] = o[i][j] * inv;
    }
}

// ---------------------------------------------------------------------------
// Launcher
// ---------------------------------------------------------------------------
extern "C" void kernel_launch(void* const* d_in, const int* in_sizes, int n_in,
                              void* d_out, int out_size)
{
    const float* query = (const float*)d_in[0];
    const float* wq = (const float*)d_in[1];
    const float* bq = (const float*)d_in[2];
    const float* wk = (const float*)d_in[3];
    const float* bk = (const float*)d_in[4];
    const float* wv = (const float*)d_in[5];
    const float* bv = (const float*)d_in[6];
    const float* wo = (const float*)d_in[7];
    const float* bo = (const float*)d_in[8];
    float* out = (float*)d_out;

    float *qb, *kb, *vb, *cb;
    cudaGetSymbolAddress((void**)&qb, g_q);
    cudaGetSymbolAddress((void**)&kb, g_k);
    cudaGetSymbolAddress((void**)&vb, g_v);
    cudaGetSymbolAddress((void**)&cb, g_ctx);

    const int gemm_smem = 4 * OPBYTES;   // 64 KB
    cudaFuncSetAttribute(gemm_mma_tf32, cudaFuncAttributeMaxDynamicSharedMemorySize, gemm_smem);

    dim3 ggrid(E_ / 128, M_ / 128);   // (8, 32)

    gemm_mma_tf32<<<ggrid, 256, gemm_smem>>>(query, wq, bq, qb, SCALING_);
    gemm_mma_tf32<<<ggrid, 256, gemm_smem>>>(query, wk, bk, kb, 1.0f);
    gemm_mma_tf32<<<ggrid, 256, gemm_smem>>>(query, wv, bv, vb, 1.0f);

    size_t asmem = (size_t)(ATT_BQ + ATT_TK + ATT_TK + ATT_BQ) * ATT_PAD * sizeof(float);
    cudaFuncSetAttribute(attn_flash, cudaFuncAttributeMaxDynamicSharedMemorySize, (int)asmem);
    attn_flash<<<dim3(S_ / ATT_BQ, H_, B_), 256, asmem>>>(qb, kb, vb, cb);

    gemm_mma_tf32<<<ggrid, 256, gemm_smem>>>(cb, wo, bo, out, 1.0f);
}

// round 4
// speedup vs baseline: 3.5827x; 2.2307x over previous
#include <cuda_runtime.h>
#include <cstdint>

// Problem dims (fixed by the reference)
#define S_ 2048
#define B_ 2
#define E_ 1024
#define H_ 16
#define DH_ 64
#define M_ (S_ * B_)        // 4096 rows for the projections
#define SCALING_ 0.125f     // DH^-0.5

// ---------------------------------------------------------------------------
// Scratch (allocation-free rule: __device__ globals)
// ---------------------------------------------------------------------------
__device__ float g_q[(size_t)M_ * E_];
__device__ float g_k[(size_t)M_ * E_];
__device__ float g_vt[(size_t)M_ * E_];    // V transposed: [b][h][d(64)][s(2048)]
__device__ float g_ctx[(size_t)M_ * E_];

// ---------------------------------------------------------------------------
// Baseline-PTX tensor helpers (work on .target sm_103 — no 'a' features)
// ---------------------------------------------------------------------------
__device__ __forceinline__ uint32_t smem_u32(const void* p) {
    uint32_t a;
    asm("{ .reg .u64 t; cvta.to.shared.u64 t, %1; cvt.u32.u64 %0, t; }"
        : "=r"(a) : "l"(p));
    return a;
}

__device__ __forceinline__ uint32_t cvt_tf32(float x) {
    uint32_t r;
    asm("cvt.rna.tf32.f32 %0, %1;" : "=r"(r) : "f"(x));
    return r;
}

__device__ __forceinline__ void ldsm_x4(uint32_t addr, uint32_t& r0, uint32_t& r1,
                                        uint32_t& r2, uint32_t& r3) {
    asm volatile("ldmatrix.sync.aligned.m8n8.x4.shared.b16 {%0,%1,%2,%3}, [%4];"
                 : "=r"(r0), "=r"(r1), "=r"(r2), "=r"(r3) : "r"(addr));
}

__device__ __forceinline__ void mma_tf32(float* d, const uint32_t* a, const uint32_t* b) {
    asm volatile(
        "mma.sync.aligned.m16n8k8.row.col.f32.tf32.tf32.f32 "
        "{%0,%1,%2,%3}, {%4,%5,%6,%7}, {%8,%9}, {%0,%1,%2,%3};"
        : "+f"(d[0]), "+f"(d[1]), "+f"(d[2]), "+f"(d[3])
        : "r"(a[0]), "r"(a[1]), "r"(a[2]), "r"(a[3]), "r"(b[0]), "r"(b[1]));
}

#define CP_ASYNC16(dst, src) \
    asm volatile("cp.async.cg.shared.global [%0], [%1], 16;" \
                 :: "r"(dst), "l"(src) : "memory")
#define CP_COMMIT() asm volatile("cp.async.commit_group;" ::: "memory")
#define CP_WAIT1()  asm volatile("cp.async.wait_group 1;" ::: "memory")
#define CP_WAIT0()  asm volatile("cp.async.wait_group 0;" ::: "memory")

__device__ __forceinline__ uint32_t sw128(uint32_t off) {
    return off ^ ((off >> 3) & 0x70);
}

// ---------------------------------------------------------------------------
// mma.sync tf32 GEMM (NT): C[m][n] = alpha * (sum_k A[m][k]*W[n][k] + bias[n])
// Optional transposed epilogue writing Cvt[b][h][d][s] (for the V projection).
// ---------------------------------------------------------------------------
#define GK 1024
#define BK 32
#define NCH (GK / BK)            // 32
#define OPBYTES (128 * BK * 4)   // 16 KB per operand per buffer
#define GEMM_SMEM 69632          // max(4*OPBYTES, 128*132*4 + pad)

__global__ __launch_bounds__(256, 2)
void gemm_mma_tf32(const float* __restrict__ A, const float* __restrict__ W,
                   const float* __restrict__ bias, float* __restrict__ C,
                   float alpha, int store_vt)
{
    extern __shared__ __align__(128) char smg[];
    const uint32_t sb = smem_u32(smg);
    const uint32_t aB[2] = { sb, sb + 2 * OPBYTES };
    const uint32_t bB[2] = { sb + OPBYTES, sb + 3 * OPBYTES };

    const int tid = threadIdx.x;
    const int wid = tid >> 5;
    const int lane = tid & 31;
    const int warp_m = wid & 1;
    const int warp_n = wid >> 1;
    const int bx = blockIdx.x;
    const int by = blockIdx.y;

    const float* Ap = A + (size_t)(by * 128) * GK;
    const float* Wp = W + (size_t)(bx * 128) * GK;

    const int ldrow = tid >> 3;
    const int ldc16 = tid & 7;

    const int a_row_base = warp_m * 64 + (lane & 15);
    const int a_hi = (lane & 16) ? 1 : 0;
    const int b_row_base = warp_n * 32 + (lane & 7) + ((lane & 16) >> 1);
    const int b_hi = (lane & 8) ? 1 : 0;

    float acc[4][4][4];
#pragma unroll
    for (int i = 0; i < 4; ++i)
#pragma unroll
        for (int j = 0; j < 4; ++j)
#pragma unroll
            for (int r = 0; r < 4; ++r) acc[i][j][r] = 0.0f;

    auto issue = [&](int c, int buf) {
#pragma unroll
        for (int i = 0; i < 4; ++i) {
            int row = ldrow + i * 32;
            uint32_t sw = sw128((uint32_t)(row * 128 + ldc16 * 16));
            const float* ga = Ap + (size_t)row * GK + c * BK + ldc16 * 4;
            const float* gw = Wp + (size_t)row * GK + c * BK + ldc16 * 4;
            CP_ASYNC16(aB[buf] + sw, ga);
            CP_ASYNC16(bB[buf] + sw, gw);
        }
    };

    issue(0, 0); CP_COMMIT();
    issue(1, 1); CP_COMMIT();

    for (int c = 0; c < NCH; ++c) {
        const int buf = c & 1;
        CP_WAIT1();
        __syncthreads();

#pragma unroll
        for (int s = 0; s < 4; ++s) {
            uint32_t bfr[4][2];
#pragma unroll
            for (int nfp = 0; nfp < 2; ++nfp) {
                int row = b_row_base + nfp * 16;
                uint32_t off = (uint32_t)(row * 128 + (s * 2 + b_hi) * 16);
                uint32_t r0, r1, r2, r3;
                ldsm_x4(bB[buf] + sw128(off), r0, r1, r2, r3);
                bfr[2 * nfp + 0][0] = cvt_tf32(__uint_as_float(r0));
                bfr[2 * nfp + 0][1] = cvt_tf32(__uint_as_float(r1));
                bfr[2 * nfp + 1][0] = cvt_tf32(__uint_as_float(r2));
                bfr[2 * nfp + 1][1] = cvt_tf32(__uint_as_float(r3));
            }
#pragma unroll
            for (int mf = 0; mf < 4; ++mf) {
                int row = a_row_base + mf * 16;
                uint32_t off = (uint32_t)(row * 128 + (s * 2 + a_hi) * 16);
                uint32_t afr[4];
                ldsm_x4(aB[buf] + sw128(off), afr[0], afr[1], afr[2], afr[3]);
#pragma unroll
                for (int r = 0; r < 4; ++r) afr[r] = cvt_tf32(__uint_as_float(afr[r]));
#pragma unroll
                for (int nf = 0; nf < 4; ++nf)
                    mma_tf32(acc[mf][nf], afr, bfr[nf]);
            }
        }
        __syncthreads();
        if (c + 2 < NCH) issue(c + 2, buf);
        CP_COMMIT();
    }

    const int gq = lane >> 2;
    const int tg = lane & 3;

    if (!store_vt) {
#pragma unroll
        for (int nf = 0; nf < 4; ++nf) {
            const int col = bx * 128 + warp_n * 32 + nf * 8 + 2 * tg;
            const float bv0 = bias[col], bv1 = bias[col + 1];
#pragma unroll
            for (int mf = 0; mf < 4; ++mf) {
                const int r0 = by * 128 + warp_m * 64 + mf * 16 + gq;
                float2 lo, hi;
                lo.x = alpha * (acc[mf][nf][0] + bv0);
                lo.y = alpha * (acc[mf][nf][1] + bv1);
                hi.x = alpha * (acc[mf][nf][2] + bv0);
                hi.y = alpha * (acc[mf][nf][3] + bv1);
                *(float2*)(C + (size_t)r0 * E_ + col) = lo;
                *(float2*)(C + (size_t)(r0 + 8) * E_ + col) = hi;
            }
        }
        return;
    }

    // --- transposed epilogue: stage to smem, write C as [b][h][d][s] ---
    CP_WAIT0();
    __syncthreads();
    float* Cs = (float*)smg;     // [128][132]
#pragma unroll
    for (int nf = 0; nf < 4; ++nf) {
        const int colL = warp_n * 32 + nf * 8 + 2 * tg;
        const int colG = bx * 128 + colL;
        const float bv0 = bias[colG], bv1 = bias[colG + 1];
#pragma unroll
        for (int mf = 0; mf < 4; ++mf) {
            const int r0 = warp_m * 64 + mf * 16 + gq;
            Cs[r0 * 132 + colL]           = acc[mf][nf][0] + bv0;
            Cs[r0 * 132 + colL + 1]       = acc[mf][nf][1] + bv1;
            Cs[(r0 + 8) * 132 + colL]     = acc[mf][nf][2] + bv0;
            Cs[(r0 + 8) * 132 + colL + 1] = acc[mf][nf][3] + bv1;
        }
    }
    __syncthreads();
    {
        const int col = tid >> 1;          // 0..127 (local n)
        const int b = tid & 1;
        const int h = bx * 2 + (col >> 6); // global head
        const int d = col & 63;
        float* dst = C + ((size_t)(b * H_ + h) * DH_ + d) * S_ + by * 64;
#pragma unroll
        for (int j = 0; j < 16; ++j) {
            float4 v;
            v.x = Cs[((4 * j + 0) * 2 + b) * 132 + col];
            v.y = Cs[((4 * j + 1) * 2 + b) * 132 + col];
            v.z = Cs[((4 * j + 2) * 2 + b) * 132 + col];
            v.w = Cs[((4 * j + 3) * 2 + b) * 132 + col];
            *(float4*)(dst + 4 * j) = v;
        }
    }
}

// ---------------------------------------------------------------------------
// Tensor-core flash attention (tf32 mma.sync).
// CTA = (q-tile 128, head, batch); 8 warps x 16 q-rows; K-tiles of 128,
// cp.async double buffered. P round-trips through warp-private smem.
// ---------------------------------------------------------------------------
#define AQ 128
#define AK 128
#define NKT (S_ / AK)        // 16

// smem byte offsets
#define SQ_  0
#define SK0_ (32 * 1024)
#define SK1_ (64 * 1024)
#define SV0_ (96 * 1024)
#define SV1_ (128 * 1024)
#define SP_  (160 * 1024)
#define ASMEM (224 * 1024)

__global__ __launch_bounds__(256, 1)
void attn_mma(const float* __restrict__ Qg, const float* __restrict__ Kg,
              const float* __restrict__ Vtg, float* __restrict__ Ctx)
{
    extern __shared__ __align__(128) char sma[];
    const uint32_t sb = smem_u32(sma);
    const int tid = threadIdx.x;
    const int wid = tid >> 5;
    const int lane = tid & 31;
    const int qt = blockIdx.x;
    const int h  = blockIdx.y;
    const int b  = blockIdx.z;

    // ---- cp.async tile loaders (2048 16B-chunks each, 8 per thread)
    auto issue_qk = [&](uint32_t base, const float* g, int row0m /*global m of row0*/) {
#pragma unroll
        for (int i = 0; i < 8; ++i) {
            int idx = tid + 256 * i;
            int row = idx >> 4, c = idx & 15;
            uint32_t dst = base + (uint32_t)(row * 256 + ((c ^ (row & 7)) << 4));
            const float* src = g + (size_t)((row0m + row) * 2 + b) * E_ + h * DH_ + c * 4;
            CP_ASYNC16(dst, src);
        }
    };
    auto issue_v = [&](uint32_t base, int kt) {
#pragma unroll
        for (int i = 0; i < 8; ++i) {
            int idx = tid + 256 * i;
            int row = idx >> 5, c = idx & 31;     // row = d
            uint32_t dst = base + (uint32_t)(row * 512 + ((c ^ (row & 7)) << 4));
            const float* src = Vtg + ((size_t)(b * H_ + h) * DH_ + row) * S_ + kt * AK + c * 4;
            CP_ASYNC16(dst, src);
        }
    };
    // in-smem tf32 rounding pass (one 16B chunk per iter)
    auto cvt_qk = [&](uint32_t base) {
#pragma unroll
        for (int i = 0; i < 8; ++i) {
            int idx = tid + 256 * i;
            int row = idx >> 4, c = idx & 15;
            uint32_t a = base + (uint32_t)(row * 256 + ((c ^ (row & 7)) << 4));
            uint32_t x0, x1, x2, x3;
            asm volatile("ld.shared.v4.b32 {%0,%1,%2,%3}, [%4];"
                         : "=r"(x0), "=r"(x1), "=r"(x2), "=r"(x3) : "r"(a));
            x0 = cvt_tf32(__uint_as_float(x0)); x1 = cvt_tf32(__uint_as_float(x1));
            x2 = cvt_tf32(__uint_as_float(x2)); x3 = cvt_tf32(__uint_as_float(x3));
            asm volatile("st.shared.v4.b32 [%0], {%1,%2,%3,%4};"
                         :: "r"(a), "r"(x0), "r"(x1), "r"(x2), "r"(x3) : "memory");
        }
    };
    auto cvt_v = [&](uint32_t base) {
#pragma unroll
        for (int i = 0; i < 8; ++i) {
            int idx = tid + 256 * i;
            int row = idx >> 5, c = idx & 31;
            uint32_t a = base + (uint32_t)(row * 512 + ((c ^ (row & 7)) << 4));
            uint32_t x0, x1, x2, x3;
            asm volatile("ld.shared.v4.b32 {%0,%1,%2,%3}, [%4];"
                         : "=r"(x0), "=r"(x1), "=r"(x2), "=r"(x3) : "r"(a));
            x0 = cvt_tf32(__uint_as_float(x0)); x1 = cvt_tf32(__uint_as_float(x1));
            x2 = cvt_tf32(__uint_as_float(x2)); x3 = cvt_tf32(__uint_as_float(x3));
            asm volatile("st.shared.v4.b32 [%0], {%1,%2,%3,%4};"
                         :: "r"(a), "r"(x0), "r"(x1), "r"(x2), "r"(x3) : "memory");
        }
    };

    const uint32_t kbuf[2] = { sb + SK0_, sb + SK1_ };
    const uint32_t vbuf[2] = { sb + SV0_, sb + SV1_ };

    issue_qk(sb + SQ_, Qg, qt * AQ);
    issue_qk(kbuf[0], Kg, 0);
    issue_v(vbuf[0], 0);
    CP_COMMIT();
    issue_qk(kbuf[1], Kg, AK);
    issue_v(vbuf[1], 1);
    CP_COMMIT();

    // fragment addressing (identical mapping to the verified GEMM)
    const int a_row = wid * 16 + (lane & 15);
    const int a_hi = (lane & 16) ? 1 : 0;
    const int b_row = (lane & 7) + ((lane & 16) >> 1);
    const int b_hi = (lane & 8) ? 1 : 0;

    float oc[8][4];
#pragma unroll
    for (int n = 0; n < 8; ++n)
#pragma unroll
        for (int r = 0; r < 4; ++r) oc[n][r] = 0.0f;
    float m0 = -1e30f, m1 = -1e30f, l0 = 0.0f, l1 = 0.0f;

    CP_WAIT1();
    __syncthreads();
    cvt_qk(sb + SQ_);
    cvt_qk(kbuf[0]);
    cvt_v(vbuf[0]);
    __syncthreads();

    for (int kt = 0; kt < NKT; ++kt) {
        const int buf = kt & 1;

        // ---- S = Q K^T : 16 n-frags x 4 regs
        float sc[16][4];
#pragma unroll
        for (int n = 0; n < 16; ++n)
#pragma unroll
            for (int r = 0; r < 4; ++r) sc[n][r] = 0.0f;

#pragma unroll
        for (int s = 0; s < 8; ++s) {
            uint32_t af[4];
            {
                uint32_t c = (uint32_t)(2 * s + a_hi);
                uint32_t addr = sb + SQ_ + (uint32_t)(a_row * 256) + ((c ^ (a_row & 7)) << 4);
                ldsm_x4(addr, af[0], af[1], af[2], af[3]);
            }
#pragma unroll
            for (int g = 0; g < 8; ++g) {
                int row = g * 16 + b_row;
                uint32_t c = (uint32_t)(2 * s + b_hi);
                uint32_t addr = kbuf[buf] + (uint32_t)(row * 256) + ((c ^ (row & 7)) << 4);
                uint32_t r0, r1, r2, r3;
                ldsm_x4(addr, r0, r1, r2, r3);
                uint32_t bfr0[2] = { r0, r1 };
                uint32_t bfr1[2] = { r2, r3 };
                mma_tf32(sc[2 * g + 0], af, bfr0);
                mma_tf32(sc[2 * g + 1], af, bfr1);
            }
        }

        // ---- online softmax (rows L/4 and L/4+8 of this warp's 16)
        float mx0 = -1e30f, mx1 = -1e30f;
#pragma unroll
        for (int n = 0; n < 16; ++n) {
            mx0 = fmaxf(mx0, fmaxf(sc[n][0], sc[n][1]));
            mx1 = fmaxf(mx1, fmaxf(sc[n][2], sc[n][3]));
        }
        mx0 = fmaxf(mx0, __shfl_xor_sync(0xffffffffu, mx0, 1));
        mx0 = fmaxf(mx0, __shfl_xor_sync(0xffffffffu, mx0, 2));
        mx1 = fmaxf(mx1, __shfl_xor_sync(0xffffffffu, mx1, 1));
        mx1 = fmaxf(mx1, __shfl_xor_sync(0xffffffffu, mx1, 2));
        const float mn0 = fmaxf(m0, mx0), mn1 = fmaxf(m1, mx1);
        const float corr0 = __expf(m0 - mn0), corr1 = __expf(m1 - mn1);
        m0 = mn0; m1 = mn1;
#pragma unroll
        for (int n = 0; n < 8; ++n) {
            oc[n][0] *= corr0; oc[n][1] *= corr0;
            oc[n][2] *= corr1; oc[n][3] *= corr1;
        }

        const int prow0 = wid * 16 + (lane >> 2);
        const int prow1 = prow0 + 8;
        float rs0 = 0.0f, rs1 = 0.0f;
        __syncwarp();
#pragma unroll
        for (int n = 0; n < 16; ++n) {
            float p00 = __expf(sc[n][0] - mn0);
            float p01 = __expf(sc[n][1] - mn0);
            float p10 = __expf(sc[n][2] - mn1);
            float p11 = __expf(sc[n][3] - mn1);
            rs0 += p00 + p01; rs1 += p10 + p11;
            const int col = n * 8 + 2 * (lane & 3);
            const uint32_t c = (uint32_t)(col >> 2);
            const uint32_t wb = (uint32_t)((col & 3) * 4);
            uint32_t a0 = sb + SP_ + (uint32_t)(prow0 * 512) + ((c ^ (prow0 & 7)) << 4) + wb;
            uint32_t a1 = sb + SP_ + (uint32_t)(prow1 * 512) + ((c ^ (prow1 & 7)) << 4) + wb;
            asm volatile("st.shared.v2.b32 [%0], {%1,%2};"
                         :: "r"(a0), "r"(cvt_tf32(p00)), "r"(cvt_tf32(p01)) : "memory");
            asm volatile("st.shared.v2.b32 [%0], {%1,%2};"
                         :: "r"(a1), "r"(cvt_tf32(p10)), "r"(cvt_tf32(p11)) : "memory");
        }
        rs0 += __shfl_xor_sync(0xffffffffu, rs0, 1);
        rs0 += __shfl_xor_sync(0xffffffffu, rs0, 2);
        rs1 += __shfl_xor_sync(0xffffffffu, rs1, 1);
        rs1 += __shfl_xor_sync(0xffffffffu, rs1, 2);
        l0 = l0 * corr0 + rs0;
        l1 = l1 * corr1 + rs1;
        __syncwarp();

        // ---- O += P V : A = P (k=128 -> 16 steps), B = Vt rows (n = d)
#pragma unroll
        for (int s = 0; s < 16; ++s) {
            uint32_t af[4];
            {
                int row = wid * 16 + (lane & 15);
                uint32_t c = (uint32_t)(2 * s + a_hi);
                uint32_t addr = sb + SP_ + (uint32_t)(row * 512) + ((c ^ (row & 7)) << 4);
                ldsm_x4(addr, af[0], af[1], af[2], af[3]);
            }
#pragma unroll
            for (int g = 0; g < 4; ++g) {
                int row = g * 16 + b_row;
                uint32_t c = (uint32_t)(2 * s + b_hi);
                uint32_t addr = vbuf[buf] + (uint32_t)(row * 512) + ((c ^ (row & 7)) << 4);
                uint32_t r0, r1, r2, r3;
                ldsm_x4(addr, r0, r1, r2, r3);
                uint32_t bfr0[2] = { r0, r1 };
                uint32_t bfr1[2] = { r2, r3 };
                mma_tf32(oc[2 * g + 0], af, bfr0);
                mma_tf32(oc[2 * g + 1], af, bfr1);
            }
        }

        __syncthreads();                       // everyone done reading buf
        if (kt + 2 < NKT) {
            issue_qk(kbuf[buf], Kg, (kt + 2) * AK);
            issue_v(vbuf[buf], kt + 2);
        }
        CP_COMMIT();
        if (kt + 1 < NKT) {
            CP_WAIT1();                        // tile kt+1 landed
            cvt_qk(kbuf[buf ^ 1]);
            cvt_v(vbuf[buf ^ 1]);
            __syncthreads();
        }
    }

    // ---- epilogue: ctx[(q*B+b)*E + h*64 + d]
    const float inv0 = 1.0f / l0, inv1 = 1.0f / l1;
    const int q0 = qt * AQ + wid * 16 + (lane >> 2);
    const int tg = lane & 3;
#pragma unroll
    for (int n = 0; n < 8; ++n) {
        const int col = h * DH_ + n * 8 + 2 * tg;
        float2 lo, hi;
        lo.x = oc[n][0] * inv0; lo.y = oc[n][1] * inv0;
        hi.x = oc[n][2] * inv1; hi.y = oc[n][3] * inv1;
        *(float2*)(Ctx + (size_t)(q0 * 2 + b) * E_ + col) = lo;
        *(float2*)(Ctx + (size_t)((q0 + 8) * 2 + b) * E_ + col) = hi;
    }
}

// ---------------------------------------------------------------------------
// Launcher
// ---------------------------------------------------------------------------
extern "C" void kernel_launch(void* const* d_in, const int* in_sizes, int n_in,
                              void* d_out, int out_size)
{
    const float* query = (const float*)d_in[0];
    const float* wq = (const float*)d_in[1];
    const float* bq = (const float*)d_in[2];
    const float* wk = (const float*)d_in[3];
    const float* bk = (const float*)d_in[4];
    const float* wv = (const float*)d_in[5];
    const float* bv = (const float*)d_in[6];
    const float* wo = (const float*)d_in[7];
    const float* bo = (const float*)d_in[8];
    float* out = (float*)d_out;

    float *qb, *kb, *vtb, *cb;
    cudaGetSymbolAddress((void**)&qb, g_q);
    cudaGetSymbolAddress((void**)&kb, g_k);
    cudaGetSymbolAddress((void**)&vtb, g_vt);
    cudaGetSymbolAddress((void**)&cb, g_ctx);

    cudaFuncSetAttribute(gemm_mma_tf32, cudaFuncAttributeMaxDynamicSharedMemorySize, GEMM_SMEM);
    cudaFuncSetAttribute(attn_mma, cudaFuncAttributeMaxDynamicSharedMemorySize, ASMEM);

    dim3 ggrid(E_ / 128, M_ / 128);   // (8, 32)

    gemm_mma_tf32<<<ggrid, 256, GEMM_SMEM>>>(query, wq, bq, qb, SCALING_, 0);
    gemm_mma_tf32<<<ggrid, 256, GEMM_SMEM>>>(query, wk, bk, kb, 1.0f, 0);
    gemm_mma_tf32<<<ggrid, 256, GEMM_SMEM>>>(query, wv, bv, vtb, 1.0f, 1);

    attn_mma<<<dim3(S_ / AQ, H_, B_), 256, ASMEM>>>(qb, kb, vtb, cb);

    gemm_mma_tf32<<<ggrid, 256, GEMM_SMEM>>>(cb, wo, bo, out, 1.0f, 0);
}

// round 5
// speedup vs baseline: 4.2005x; 1.1724x over previous
#include <cuda_runtime.h>
#include <cstdint>

// Problem dims (fixed by the reference)
#define S_ 2048
#define B_ 2
#define E_ 1024
#define H_ 16
#define DH_ 64
#define M_ (S_ * B_)
#define SCALING_ 0.125f

// ---------------------------------------------------------------------------
// Scratch (allocation-free rule: __device__ globals)
// ---------------------------------------------------------------------------
__device__ float g_q[(size_t)M_ * E_];
__device__ float g_k[(size_t)M_ * E_];
__device__ float g_vt[(size_t)M_ * E_];    // V transposed: [b][h][d(64)][s(2048)]
__device__ float g_ctx[(size_t)M_ * E_];

// ---------------------------------------------------------------------------
// Baseline-PTX tensor helpers (.target sm_103 safe)
// ---------------------------------------------------------------------------
__device__ __forceinline__ uint32_t smem_u32(const void* p) {
    uint32_t a;
    asm("{ .reg .u64 t; cvta.to.shared.u64 t, %1; cvt.u32.u64 %0, t; }"
        : "=r"(a) : "l"(p));
    return a;
}

__device__ __forceinline__ uint32_t cvt_tf32(float x) {
    uint32_t r;
    asm("cvt.rna.tf32.f32 %0, %1;" : "=r"(r) : "f"(x));
    return r;
}
__device__ __forceinline__ float round_tf32f(float x) {
    return __uint_as_float(cvt_tf32(x));
}

__device__ __forceinline__ void ldsm_x4(uint32_t addr, uint32_t& r0, uint32_t& r1,
                                        uint32_t& r2, uint32_t& r3) {
    asm volatile("ldmatrix.sync.aligned.m8n8.x4.shared.b16 {%0,%1,%2,%3}, [%4];"
                 : "=r"(r0), "=r"(r1), "=r"(r2), "=r"(r3) : "r"(addr));
}

__device__ __forceinline__ void mma_tf32(float* d, const uint32_t* a, const uint32_t* b) {
    asm volatile(
        "mma.sync.aligned.m16n8k8.row.col.f32.tf32.tf32.f32 "
        "{%0,%1,%2,%3}, {%4,%5,%6,%7}, {%8,%9}, {%0,%1,%2,%3};"
        : "+f"(d[0]), "+f"(d[1]), "+f"(d[2]), "+f"(d[3])
        : "r"(a[0]), "r"(a[1]), "r"(a[2]), "r"(a[3]), "r"(b[0]), "r"(b[1]));
}

#define CP_ASYNC16(dst, src) \
    asm volatile("cp.async.cg.shared.global [%0], [%1], 16;" \
                 :: "r"(dst), "l"(src) : "memory")
#define CP_COMMIT() asm volatile("cp.async.commit_group;" ::: "memory")
#define CP_WAIT1()  asm volatile("cp.async.wait_group 1;" ::: "memory")
#define CP_WAIT0()  asm volatile("cp.async.wait_group 0;" ::: "memory")

__device__ __forceinline__ uint32_t sw128(uint32_t off) {
    return off ^ ((off >> 3) & 0x70);
}

// ---------------------------------------------------------------------------
// mma.sync tf32 GEMM (NT): C[m][n] = alpha * (sum_k A[m][k]*W[n][k] + bias[n])
// store_vt: transposed epilogue -> Cvt[b][h][d][s] (tf32-rounded).
// round_out: round the standard-epilogue output to tf32 (for Q/K scratch).
// ---------------------------------------------------------------------------
#define GK 1024
#define BK 32
#define NCH (GK / BK)
#define OPBYTES (128 * BK * 4)
#define GEMM_SMEM 69632

__global__ __launch_bounds__(256, 2)
void gemm_mma_tf32(const float* __restrict__ A, const float* __restrict__ W,
                   const float* __restrict__ bias, float* __restrict__ C,
                   float alpha, int store_vt, int round_out)
{
    extern __shared__ __align__(128) char smg[];
    const uint32_t sb = smem_u32(smg);
    const uint32_t aB[2] = { sb, sb + 2 * OPBYTES };
    const uint32_t bB[2] = { sb + OPBYTES, sb + 3 * OPBYTES };

    const int tid = threadIdx.x;
    const int wid = tid >> 5;
    const int lane = tid & 31;
    const int warp_m = wid & 1;
    const int warp_n = wid >> 1;
    const int bx = blockIdx.x;
    const int by = blockIdx.y;

    const float* Ap = A + (size_t)(by * 128) * GK;
    const float* Wp = W + (size_t)(bx * 128) * GK;

    const int ldrow = tid >> 3;
    const int ldc16 = tid & 7;

    const int a_row_base = warp_m * 64 + (lane & 15);
    const int a_hi = (lane & 16) ? 1 : 0;
    const int b_row_base = warp_n * 32 + (lane & 7) + ((lane & 16) >> 1);
    const int b_hi = (lane & 8) ? 1 : 0;

    float acc[4][4][4];
#pragma unroll
    for (int i = 0; i < 4; ++i)
#pragma unroll
        for (int j = 0; j < 4; ++j)
#pragma unroll
            for (int r = 0; r < 4; ++r) acc[i][j][r] = 0.0f;

    auto issue = [&](int c, int buf) {
#pragma unroll
        for (int i = 0; i < 4; ++i) {
            int row = ldrow + i * 32;
            uint32_t sw = sw128((uint32_t)(row * 128 + ldc16 * 16));
            const float* ga = Ap + (size_t)row * GK + c * BK + ldc16 * 4;
            const float* gw = Wp + (size_t)row * GK + c * BK + ldc16 * 4;
            CP_ASYNC16(aB[buf] + sw, ga);
            CP_ASYNC16(bB[buf] + sw, gw);
        }
    };

    issue(0, 0); CP_COMMIT();
    issue(1, 1); CP_COMMIT();

    for (int c = 0; c < NCH; ++c) {
        const int buf = c & 1;
        CP_WAIT1();
        __syncthreads();

#pragma unroll
        for (int s = 0; s < 4; ++s) {
            uint32_t bfr[4][2];
#pragma unroll
            for (int nfp = 0; nfp < 2; ++nfp) {
                int row = b_row_base + nfp * 16;
                uint32_t off = (uint32_t)(row * 128 + (s * 2 + b_hi) * 16);
                uint32_t r0, r1, r2, r3;
                ldsm_x4(bB[buf] + sw128(off), r0, r1, r2, r3);
                bfr[2 * nfp + 0][0] = cvt_tf32(__uint_as_float(r0));
                bfr[2 * nfp + 0][1] = cvt_tf32(__uint_as_float(r1));
                bfr[2 * nfp + 1][0] = cvt_tf32(__uint_as_float(r2));
                bfr[2 * nfp + 1][1] = cvt_tf32(__uint_as_float(r3));
            }
#pragma unroll
            for (int mf = 0; mf < 4; ++mf) {
                int row = a_row_base + mf * 16;
                uint32_t off = (uint32_t)(row * 128 + (s * 2 + a_hi) * 16);
                uint32_t afr[4];
                ldsm_x4(aB[buf] + sw128(off), afr[0], afr[1], afr[2], afr[3]);
#pragma unroll
                for (int r = 0; r < 4; ++r) afr[r] = cvt_tf32(__uint_as_float(afr[r]));
#pragma unroll
                for (int nf = 0; nf < 4; ++nf)
                    mma_tf32(acc[mf][nf], afr, bfr[nf]);
            }
        }
        __syncthreads();
        if (c + 2 < NCH) issue(c + 2, buf);
        CP_COMMIT();
    }

    const int gq = lane >> 2;
    const int tg = lane & 3;

    if (!store_vt) {
#pragma unroll
        for (int nf = 0; nf < 4; ++nf) {
            const int col = bx * 128 + warp_n * 32 + nf * 8 + 2 * tg;
            const float bv0 = bias[col], bv1 = bias[col + 1];
#pragma unroll
            for (int mf = 0; mf < 4; ++mf) {
                const int r0 = by * 128 + warp_m * 64 + mf * 16 + gq;
                float2 lo, hi;
                lo.x = alpha * (acc[mf][nf][0] + bv0);
                lo.y = alpha * (acc[mf][nf][1] + bv1);
                hi.x = alpha * (acc[mf][nf][2] + bv0);
                hi.y = alpha * (acc[mf][nf][3] + bv1);
                if (round_out) {
                    lo.x = round_tf32f(lo.x); lo.y = round_tf32f(lo.y);
                    hi.x = round_tf32f(hi.x); hi.y = round_tf32f(hi.y);
                }
                *(float2*)(C + (size_t)r0 * E_ + col) = lo;
                *(float2*)(C + (size_t)(r0 + 8) * E_ + col) = hi;
            }
        }
        return;
    }

    // --- transposed epilogue: stage to smem (tf32-rounded), write [b][h][d][s]
    CP_WAIT0();
    __syncthreads();
    float* Cs = (float*)smg;     // [128][132]
#pragma unroll
    for (int nf = 0; nf < 4; ++nf) {
        const int colL = warp_n * 32 + nf * 8 + 2 * tg;
        const int colG = bx * 128 + colL;
        const float bv0 = bias[colG], bv1 = bias[colG + 1];
#pragma unroll
        for (int mf = 0; mf < 4; ++mf) {
            const int r0 = warp_m * 64 + mf * 16 + gq;
            Cs[r0 * 132 + colL]           = round_tf32f(acc[mf][nf][0] + bv0);
            Cs[r0 * 132 + colL + 1]       = round_tf32f(acc[mf][nf][1] + bv1);
            Cs[(r0 + 8) * 132 + colL]     = round_tf32f(acc[mf][nf][2] + bv0);
            Cs[(r0 + 8) * 132 + colL + 1] = round_tf32f(acc[mf][nf][3] + bv1);
        }
    }
    __syncthreads();
    {
        const int col = tid >> 1;
        const int b = tid & 1;
        const int h = bx * 2 + (col >> 6);
        const int d = col & 63;
        float* dst = C + ((size_t)(b * H_ + h) * DH_ + d) * S_ + by * 64;
#pragma unroll
        for (int j = 0; j < 16; ++j) {
            float4 v;
            v.x = Cs[((4 * j + 0) * 2 + b) * 132 + col];
            v.y = Cs[((4 * j + 1) * 2 + b) * 132 + col];
            v.z = Cs[((4 * j + 2) * 2 + b) * 132 + col];
            v.w = Cs[((4 * j + 3) * 2 + b) * 132 + col];
            *(float4*)(dst + 4 * j) = v;
        }
    }
}

// ---------------------------------------------------------------------------
// Tensor-core flash attention v2 (tf32 mma.sync).
// CTA = (q-tile 256, head, batch); 8 warps x 32 q-rows (2 m-frags -> 2x B reuse);
// K-tiles of 64, cp.async double buffered. Inputs pre-rounded to tf32 by the
// producer GEMMs (no in-smem cvt passes).
// ---------------------------------------------------------------------------
#define AQ 256
#define AK 64
#define NKT (S_ / AK)        // 32

// smem byte offsets (rows of 256B = 64 floats everywhere)
#define SQ_  0
#define SK0_ (64 * 1024)
#define SK1_ (80 * 1024)
#define SV0_ (96 * 1024)
#define SV1_ (112 * 1024)
#define SP_  (128 * 1024)
#define ASMEM (192 * 1024)

__global__ __launch_bounds__(256, 1)
void attn_mma(const float* __restrict__ Qg, const float* __restrict__ Kg,
              const float* __restrict__ Vtg, float* __restrict__ Ctx)
{
    extern __shared__ __align__(128) char sma[];
    const uint32_t sb = smem_u32(sma);
    const int tid = threadIdx.x;
    const int wid = tid >> 5;
    const int lane = tid & 31;
    const int qt = blockIdx.x;   // 0..7
    const int h  = blockIdx.y;
    const int b  = blockIdx.z;

    // ---- loaders (rows of 64 floats = 16 chunks of 16B)
    auto issue_q = [&]() {
#pragma unroll
        for (int i = 0; i < 16; ++i) {
            int idx = tid + 256 * i;
            int row = idx >> 4, c = idx & 15;
            uint32_t dst = sb + SQ_ + (uint32_t)(row * 256 + ((c ^ (row & 7)) << 4));
            const float* src = Qg + (size_t)((qt * AQ + row) * 2 + b) * E_ + h * DH_ + c * 4;
            CP_ASYNC16(dst, src);
        }
    };
    auto issue_k = [&](uint32_t base, int kt) {
#pragma unroll
        for (int i = 0; i < 4; ++i) {
            int idx = tid + 256 * i;
            int row = idx >> 4, c = idx & 15;
            uint32_t dst = base + (uint32_t)(row * 256 + ((c ^ (row & 7)) << 4));
            const float* src = Kg + (size_t)((kt * AK + row) * 2 + b) * E_ + h * DH_ + c * 4;
            CP_ASYNC16(dst, src);
        }
    };
    auto issue_v = [&](uint32_t base, int kt) {
#pragma unroll
        for (int i = 0; i < 4; ++i) {
            int idx = tid + 256 * i;
            int row = idx >> 4, c = idx & 15;   // row = d
            uint32_t dst = base + (uint32_t)(row * 256 + ((c ^ (row & 7)) << 4));
            const float* src = Vtg + ((size_t)(b * H_ + h) * DH_ + row) * S_ + kt * AK + c * 4;
            CP_ASYNC16(dst, src);
        }
    };

    const uint32_t kbuf[2] = { sb + SK0_, sb + SK1_ };
    const uint32_t vbuf[2] = { sb + SV0_, sb + SV1_ };

    issue_q();
    issue_k(kbuf[0], 0);
    issue_v(vbuf[0], 0);
    CP_COMMIT();
    issue_k(kbuf[1], 1);
    issue_v(vbuf[1], 1);
    CP_COMMIT();

    // fragment addressing (verified mapping)
    const int a_hi = (lane & 16) ? 1 : 0;
    const int b_row = (lane & 7) + ((lane & 16) >> 1);
    const int b_hi = (lane & 8) ? 1 : 0;
    const int arow[2] = { wid * 32 + (lane & 15), wid * 32 + 16 + (lane & 15) };

    float oc[2][8][4];
#pragma unroll
    for (int mf = 0; mf < 2; ++mf)
#pragma unroll
        for (int n = 0; n < 8; ++n)
#pragma unroll
            for (int r = 0; r < 4; ++r) oc[mf][n][r] = 0.0f;
    float mrow[2][2] = { {-1e30f, -1e30f}, {-1e30f, -1e30f} };
    float lrow[2][2] = { {0.0f, 0.0f}, {0.0f, 0.0f} };

    CP_WAIT1();
    __syncthreads();

    for (int kt = 0; kt < NKT; ++kt) {
        const int buf = kt & 1;

        // ---- S = Q K^T : 2 m-frags x 8 n-frags
        float sc[2][8][4];
#pragma unroll
        for (int mf = 0; mf < 2; ++mf)
#pragma unroll
            for (int n = 0; n < 8; ++n)
#pragma unroll
                for (int r = 0; r < 4; ++r) sc[mf][n][r] = 0.0f;

#pragma unroll
        for (int s = 0; s < 8; ++s) {
            uint32_t af[2][4];
#pragma unroll
            for (int mf = 0; mf < 2; ++mf) {
                uint32_t c = (uint32_t)(2 * s + a_hi);
                uint32_t addr = sb + SQ_ + (uint32_t)(arow[mf] * 256) + ((c ^ (arow[mf] & 7)) << 4);
                ldsm_x4(addr, af[mf][0], af[mf][1], af[mf][2], af[mf][3]);
            }
#pragma unroll
            for (int g = 0; g < 4; ++g) {
                int row = g * 16 + b_row;
                uint32_t c = (uint32_t)(2 * s + b_hi);
                uint32_t addr = kbuf[buf] + (uint32_t)(row * 256) + ((c ^ (row & 7)) << 4);
                uint32_t r0, r1, r2, r3;
                ldsm_x4(addr, r0, r1, r2, r3);
                uint32_t bfr0[2] = { r0, r1 };
                uint32_t bfr1[2] = { r2, r3 };
#pragma unroll
                for (int mf = 0; mf < 2; ++mf) {
                    mma_tf32(sc[mf][2 * g + 0], af[mf], bfr0);
                    mma_tf32(sc[mf][2 * g + 1], af[mf], bfr1);
                }
            }
        }

        // ---- online softmax + P store (per m-frag)
        __syncwarp();
#pragma unroll
        for (int mf = 0; mf < 2; ++mf) {
            float mx0 = -1e30f, mx1 = -1e30f;
#pragma unroll
            for (int n = 0; n < 8; ++n) {
                mx0 = fmaxf(mx0, fmaxf(sc[mf][n][0], sc[mf][n][1]));
                mx1 = fmaxf(mx1, fmaxf(sc[mf][n][2], sc[mf][n][3]));
            }
            mx0 = fmaxf(mx0, __shfl_xor_sync(0xffffffffu, mx0, 1));
            mx0 = fmaxf(mx0, __shfl_xor_sync(0xffffffffu, mx0, 2));
            mx1 = fmaxf(mx1, __shfl_xor_sync(0xffffffffu, mx1, 1));
            mx1 = fmaxf(mx1, __shfl_xor_sync(0xffffffffu, mx1, 2));
            const float mn0 = fmaxf(mrow[mf][0], mx0);
            const float mn1 = fmaxf(mrow[mf][1], mx1);
            const float corr0 = __expf(mrow[mf][0] - mn0);
            const float corr1 = __expf(mrow[mf][1] - mn1);
            mrow[mf][0] = mn0; mrow[mf][1] = mn1;
#pragma unroll
            for (int n = 0; n < 8; ++n) {
                oc[mf][n][0] *= corr0; oc[mf][n][1] *= corr0;
                oc[mf][n][2] *= corr1; oc[mf][n][3] *= corr1;
            }
            const int prow0 = wid * 32 + mf * 16 + (lane >> 2);
            const int prow1 = prow0 + 8;
            float rs0 = 0.0f, rs1 = 0.0f;
#pragma unroll
            for (int n = 0; n < 8; ++n) {
                float p00 = __expf(sc[mf][n][0] - mn0);
                float p01 = __expf(sc[mf][n][1] - mn0);
                float p10 = __expf(sc[mf][n][2] - mn1);
                float p11 = __expf(sc[mf][n][3] - mn1);
                rs0 += p00 + p01; rs1 += p10 + p11;
                const int col = n * 8 + 2 * (lane & 3);
                const uint32_t c = (uint32_t)(col >> 2);
                const uint32_t wb = (uint32_t)((col & 3) * 4);
                uint32_t a0 = sb + SP_ + (uint32_t)(prow0 * 256) + ((c ^ (prow0 & 7)) << 4) + wb;
                uint32_t a1 = sb + SP_ + (uint32_t)(prow1 * 256) + ((c ^ (prow1 & 7)) << 4) + wb;
                asm volatile("st.shared.v2.b32 [%0], {%1,%2};"
                             :: "r"(a0), "r"(cvt_tf32(p00)), "r"(cvt_tf32(p01)) : "memory");
                asm volatile("st.shared.v2.b32 [%0], {%1,%2};"
                             :: "r"(a1), "r"(cvt_tf32(p10)), "r"(cvt_tf32(p11)) : "memory");
            }
            rs0 += __shfl_xor_sync(0xffffffffu, rs0, 1);
            rs0 += __shfl_xor_sync(0xffffffffu, rs0, 2);
            rs1 += __shfl_xor_sync(0xffffffffu, rs1, 1);
            rs1 += __shfl_xor_sync(0xffffffffu, rs1, 2);
            lrow[mf][0] = lrow[mf][0] * corr0 + rs0;
            lrow[mf][1] = lrow[mf][1] * corr1 + rs1;
        }
        __syncwarp();

        // ---- O += P V : k = 64 keys -> 8 steps; B = Vt rows (n = d)
#pragma unroll
        for (int s = 0; s < 8; ++s) {
            uint32_t af[2][4];
#pragma unroll
            for (int mf = 0; mf < 2; ++mf) {
                uint32_t c = (uint32_t)(2 * s + a_hi);
                uint32_t addr = sb + SP_ + (uint32_t)(arow[mf] * 256) + ((c ^ (arow[mf] & 7)) << 4);
                ldsm_x4(addr, af[mf][0], af[mf][1], af[mf][2], af[mf][3]);
            }
#pragma unroll
            for (int g = 0; g < 4; ++g) {
                int row = g * 16 + b_row;
                uint32_t c = (uint32_t)(2 * s + b_hi);
                uint32_t addr = vbuf[buf] + (uint32_t)(row * 256) + ((c ^ (row & 7)) << 4);
                uint32_t r0, r1, r2, r3;
                ldsm_x4(addr, r0, r1, r2, r3);
                uint32_t bfr0[2] = { r0, r1 };
                uint32_t bfr1[2] = { r2, r3 };
#pragma unroll
                for (int mf = 0; mf < 2; ++mf) {
                    mma_tf32(oc[mf][2 * g + 0], af[mf], bfr0);
                    mma_tf32(oc[mf][2 * g + 1], af[mf], bfr1);
                }
            }
        }

        __syncthreads();                       // all warps done reading buf
        if (kt + 2 < NKT) {
            issue_k(kbuf[buf], kt + 2);
            issue_v(vbuf[buf], kt + 2);
        }
        CP_COMMIT();
        if (kt + 1 < NKT) {
            CP_WAIT1();
            __syncthreads();
        }
    }

    // ---- epilogue: ctx[(q*B+b)*E + h*64 + d]
    const int tg = lane & 3;
#pragma unroll
    for (int mf = 0; mf < 2; ++mf) {
        const float inv0 = 1.0f / lrow[mf][0];
        const float inv1 = 1.0f / lrow[mf][1];
        const int q0 = qt * AQ + wid * 32 + mf * 16 + (lane >> 2);
#pragma unroll
        for (int n = 0; n < 8; ++n) {
            const int col = h * DH_ + n * 8 + 2 * tg;
            float2 lo, hi;
            lo.x = oc[mf][n][0] * inv0; lo.y = oc[mf][n][1] * inv0;
            hi.x = oc[mf][n][2] * inv1; hi.y = oc[mf][n][3] * inv1;
            *(float2*)(Ctx + (size_t)(q0 * 2 + b) * E_ + col) = lo;
            *(float2*)(Ctx + (size_t)((q0 + 8) * 2 + b) * E_ + col) = hi;
        }
    }
}

// ---------------------------------------------------------------------------
// Launcher
// ---------------------------------------------------------------------------
extern "C" void kernel_launch(void* const* d_in, const int* in_sizes, int n_in,
                              void* d_out, int out_size)
{
    const float* query = (const float*)d_in[0];
    const float* wq = (const float*)d_in[1];
    const float* bq = (const float*)d_in[2];
    const float* wk = (const float*)d_in[3];
    const float* bk = (const float*)d_in[4];
    const float* wv = (const float*)d_in[5];
    const float* bv = (const float*)d_in[6];
    const float* wo = (const float*)d_in[7];
    const float* bo = (const float*)d_in[8];
    float* out = (float*)d_out;

    float *qb, *kb, *vtb, *cb;
    cudaGetSymbolAddress((void**)&qb, g_q);
    cudaGetSymbolAddress((void**)&kb, g_k);
    cudaGetSymbolAddress((void**)&vtb, g_vt);
    cudaGetSymbolAddress((void**)&cb, g_ctx);

    cudaFuncSetAttribute(gemm_mma_tf32, cudaFuncAttributeMaxDynamicSharedMemorySize, GEMM_SMEM);
    cudaFuncSetAttribute(attn_mma, cudaFuncAttributeMaxDynamicSharedMemorySize, ASMEM);

    dim3 ggrid(E_ / 128, M_ / 128);   // (8, 32)

    gemm_mma_tf32<<<ggrid, 256, GEMM_SMEM>>>(query, wq, bq, qb, SCALING_, 0, 1);
    gemm_mma_tf32<<<ggrid, 256, GEMM_SMEM>>>(query, wk, bk, kb, 1.0f, 0, 1);
    gemm_mma_tf32<<<ggrid, 256, GEMM_SMEM>>>(query, wv, bv, vtb, 1.0f, 1, 0);

    attn_mma<<<dim3(S_ / AQ, H_, B_), 256, ASMEM>>>(qb, kb, vtb, cb);

    gemm_mma_tf32<<<ggrid, 256, GEMM_SMEM>>>(cb, wo, bo, out, 1.0f, 0, 0);
}

// round 6
// speedup vs baseline: 7.7101x; 1.8355x over previous
#include <cuda_runtime.h>
#include <cuda_fp16.h>
#include <cstdint>

// Problem dims (fixed by the reference)
#define S_ 2048
#define B_ 2
#define E_ 1024
#define H_ 16
#define DH_ 64
#define M_ (S_ * B_)
#define SCALING_ 0.125f

// ---------------------------------------------------------------------------
// Scratch (allocation-free rule: __device__ globals), all fp16
// ---------------------------------------------------------------------------
__device__ __half g_hx[(size_t)M_ * E_];     // query in fp16
__device__ __half g_hwq[(size_t)E_ * E_];
__device__ __half g_hwk[(size_t)E_ * E_];
__device__ __half g_hwv[(size_t)E_ * E_];
__device__ __half g_hwo[(size_t)E_ * E_];
__device__ __half g_q[(size_t)M_ * E_];
__device__ __half g_k[(size_t)M_ * E_];
__device__ __half g_vt[(size_t)M_ * E_];     // V transposed: [b][h][d][s]
__device__ __half g_ctx[(size_t)M_ * E_];

// ---------------------------------------------------------------------------
// Helpers (.target sm_103 safe)
// ---------------------------------------------------------------------------
__device__ __forceinline__ uint32_t smem_u32(const void* p) {
    uint32_t a;
    asm("{ .reg .u64 t; cvta.to.shared.u64 t, %1; cvt.u32.u64 %0, t; }"
        : "=r"(a) : "l"(p));
    return a;
}

__device__ __forceinline__ uint32_t pack_h2(float a, float b) {
    __half2 h = __floats2half2_rn(a, b);
    return *reinterpret_cast<uint32_t*>(&h);
}

__device__ __forceinline__ void ldsm_x4(uint32_t addr, uint32_t& r0, uint32_t& r1,
                                        uint32_t& r2, uint32_t& r3) {
    asm volatile("ldmatrix.sync.aligned.m8n8.x4.shared.b16 {%0,%1,%2,%3}, [%4];"
                 : "=r"(r0), "=r"(r1), "=r"(r2), "=r"(r3) : "r"(addr));
}

__device__ __forceinline__ void mma_f16(float* d, const uint32_t* a, const uint32_t* b) {
    asm volatile(
        "mma.sync.aligned.m16n8k16.row.col.f32.f16.f16.f32 "
        "{%0,%1,%2,%3}, {%4,%5,%6,%7}, {%8,%9}, {%0,%1,%2,%3};"
        : "+f"(d[0]), "+f"(d[1]), "+f"(d[2]), "+f"(d[3])
        : "r"(a[0]), "r"(a[1]), "r"(a[2]), "r"(a[3]), "r"(b[0]), "r"(b[1]));
}

#define CP_ASYNC16(dst, src) \
    asm volatile("cp.async.cg.shared.global [%0], [%1], 16;" \
                 :: "r"(dst), "l"(src) : "memory")
#define CP_COMMIT() asm volatile("cp.async.commit_group;" ::: "memory")
#define CP_WAIT1()  asm volatile("cp.async.wait_group 1;" ::: "memory")
#define CP_WAIT0()  asm volatile("cp.async.wait_group 0;" ::: "memory")

__device__ __forceinline__ uint32_t sw128(uint32_t off) {
    return off ^ ((off >> 3) & 0x70);
}

// ---------------------------------------------------------------------------
// fp32 -> fp16 convert (vectorized)
// ---------------------------------------------------------------------------
__global__ __launch_bounds__(256)
void cvt_f32_f16(const float* __restrict__ in, __half* __restrict__ out, int n4) {
    int i = blockIdx.x * blockDim.x + threadIdx.x;
    if (i < n4) {
        float4 v = ((const float4*)in)[i];
        uint2 o;
        o.x = pack_h2(v.x, v.y);
        o.y = pack_h2(v.z, v.w);
        ((uint2*)out)[i] = o;
    }
}

// ---------------------------------------------------------------------------
// fp16 mma GEMM (NT): C[m][n] = alpha*(sum_k A[m][k]*W[n][k] + bias[n])
// A,W: half row-major [.,1024]. CTA 128x128, BK=64 halfs (128B rows),
// cp.async double buffered. 8 warps = 2(M) x 4(N), warp tile 64x32.
// mode 0: fp32 out; 1: half out; 2: half transposed out [b][h][d][s].
// ---------------------------------------------------------------------------
#define GK 1024
#define BKH 64
#define NCH (GK / BKH)            // 16
#define OPB (128 * 128)           // 16 KB per operand per buffer
#define GEMM_SMEM 69632

__global__ __launch_bounds__(256, 2)
void gemm_mma_f16(const __half* __restrict__ A, const __half* __restrict__ W,
                  const float* __restrict__ bias, void* __restrict__ Cout,
                  float alpha, int mode)
{
    extern __shared__ __align__(128) char smg[];
    const uint32_t sb = smem_u32(smg);
    const uint32_t aB[2] = { sb, sb + 2 * OPB };
    const uint32_t bB[2] = { sb + OPB, sb + 3 * OPB };

    const int tid = threadIdx.x;
    const int wid = tid >> 5;
    const int lane = tid & 31;
    const int warp_m = wid & 1;
    const int warp_n = wid >> 1;
    const int bx = blockIdx.x;
    const int by = blockIdx.y;

    const __half* Ap = A + (size_t)(by * 128) * GK;
    const __half* Wp = W + (size_t)(bx * 128) * GK;

    const int ldrow = tid >> 3;       // 0..31, +32*i
    const int ldc16 = tid & 7;

    const int a_hi = (lane & 16) ? 1 : 0;
    const int b_row_rel = (lane & 7) + ((lane & 16) >> 1);
    const int b_hi = (lane & 8) ? 1 : 0;

    float acc[4][4][4];
#pragma unroll
    for (int i = 0; i < 4; ++i)
#pragma unroll
        for (int j = 0; j < 4; ++j)
#pragma unroll
            for (int r = 0; r < 4; ++r) acc[i][j][r] = 0.0f;

    auto issue = [&](int c, int buf) {
#pragma unroll
        for (int i = 0; i < 4; ++i) {
            int row = ldrow + i * 32;
            uint32_t sw = sw128((uint32_t)(row * 128 + ldc16 * 16));
            const __half* ga = Ap + (size_t)row * GK + c * BKH + ldc16 * 8;
            const __half* gw = Wp + (size_t)row * GK + c * BKH + ldc16 * 8;
            CP_ASYNC16(aB[buf] + sw, ga);
            CP_ASYNC16(bB[buf] + sw, gw);
        }
    };

    issue(0, 0); CP_COMMIT();
    issue(1, 1); CP_COMMIT();

    for (int c = 0; c < NCH; ++c) {
        const int buf = c & 1;
        CP_WAIT1();
        __syncthreads();

#pragma unroll
        for (int s = 0; s < 4; ++s) {          // k16 steps within BK=64
            uint32_t bfr[4][2];
#pragma unroll
            for (int nfp = 0; nfp < 2; ++nfp) {
                int row = warp_n * 32 + nfp * 16 + b_row_rel;
                uint32_t off = (uint32_t)(row * 128 + (2 * s + b_hi) * 16);
                uint32_t r0, r1, r2, r3;
                ldsm_x4(bB[buf] + sw128(off), r0, r1, r2, r3);
                bfr[2 * nfp + 0][0] = r0; bfr[2 * nfp + 0][1] = r1;
                bfr[2 * nfp + 1][0] = r2; bfr[2 * nfp + 1][1] = r3;
            }
#pragma unroll
            for (int mf = 0; mf < 4; ++mf) {
                int row = warp_m * 64 + mf * 16 + (lane & 15);
                uint32_t off = (uint32_t)(row * 128 + (2 * s + a_hi) * 16);
                uint32_t af[4];
                ldsm_x4(aB[buf] + sw128(off), af[0], af[1], af[2], af[3]);
#pragma unroll
                for (int nf = 0; nf < 4; ++nf)
                    mma_f16(acc[mf][nf], af, bfr[nf]);
            }
        }
        __syncthreads();
        if (c + 2 < NCH) issue(c + 2, buf);
        CP_COMMIT();
    }

    const int gq = lane >> 2;
    const int tg = lane & 3;

    if (mode == 0) {
        float* C = (float*)Cout;
#pragma unroll
        for (int nf = 0; nf < 4; ++nf) {
            const int col = bx * 128 + warp_n * 32 + nf * 8 + 2 * tg;
            const float bv0 = bias[col], bv1 = bias[col + 1];
#pragma unroll
            for (int mf = 0; mf < 4; ++mf) {
                const int r0 = by * 128 + warp_m * 64 + mf * 16 + gq;
                float2 lo, hi;
                lo.x = alpha * (acc[mf][nf][0] + bv0);
                lo.y = alpha * (acc[mf][nf][1] + bv1);
                hi.x = alpha * (acc[mf][nf][2] + bv0);
                hi.y = alpha * (acc[mf][nf][3] + bv1);
                *(float2*)(C + (size_t)r0 * E_ + col) = lo;
                *(float2*)(C + (size_t)(r0 + 8) * E_ + col) = hi;
            }
        }
        return;
    }
    if (mode == 1) {
        __half* C = (__half*)Cout;
#pragma unroll
        for (int nf = 0; nf < 4; ++nf) {
            const int col = bx * 128 + warp_n * 32 + nf * 8 + 2 * tg;
            const float bv0 = bias[col], bv1 = bias[col + 1];
#pragma unroll
            for (int mf = 0; mf < 4; ++mf) {
                const int r0 = by * 128 + warp_m * 64 + mf * 16 + gq;
                uint32_t lo = pack_h2(alpha * (acc[mf][nf][0] + bv0),
                                      alpha * (acc[mf][nf][1] + bv1));
                uint32_t hi = pack_h2(alpha * (acc[mf][nf][2] + bv0),
                                      alpha * (acc[mf][nf][3] + bv1));
                *(uint32_t*)(C + (size_t)r0 * E_ + col) = lo;
                *(uint32_t*)(C + (size_t)(r0 + 8) * E_ + col) = hi;
            }
        }
        return;
    }

    // mode 2: transposed epilogue -> Cvt[b][h][d][s] as half
    CP_WAIT0();
    __syncthreads();
    float* Cs = (float*)smg;     // [128][132]
#pragma unroll
    for (int nf = 0; nf < 4; ++nf) {
        const int colL = warp_n * 32 + nf * 8 + 2 * tg;
        const int colG = bx * 128 + colL;
        const float bv0 = bias[colG], bv1 = bias[colG + 1];
#pragma unroll
        for (int mf = 0; mf < 4; ++mf) {
            const int r0 = warp_m * 64 + mf * 16 + gq;
            Cs[r0 * 132 + colL]           = acc[mf][nf][0] + bv0;
            Cs[r0 * 132 + colL + 1]       = acc[mf][nf][1] + bv1;
            Cs[(r0 + 8) * 132 + colL]     = acc[mf][nf][2] + bv0;
            Cs[(r0 + 8) * 132 + colL + 1] = acc[mf][nf][3] + bv1;
        }
    }
    __syncthreads();
    {
        __half* C = (__half*)Cout;
        const int col = tid >> 1;          // local n 0..127
        const int b = tid & 1;
        const int h = bx * 2 + (col >> 6);
        const int d = col & 63;
        __half* dst = C + ((size_t)(b * H_ + h) * DH_ + d) * S_ + by * 64;
#pragma unroll
        for (int j = 0; j < 16; ++j) {
            uint2 o;
            o.x = pack_h2(Cs[((4 * j + 0) * 2 + b) * 132 + col],
                          Cs[((4 * j + 1) * 2 + b) * 132 + col]);
            o.y = pack_h2(Cs[((4 * j + 2) * 2 + b) * 132 + col],
                          Cs[((4 * j + 3) * 2 + b) * 132 + col]);
            *(uint2*)(dst + 4 * j) = o;
        }
    }
}

// ---------------------------------------------------------------------------
// fp16 tensor-core flash attention. CTA = (q-tile 256, head, batch);
// 8 warps x 32 q-rows; K-tiles of 64, cp.async double buffered.
// P never touches smem: S-accumulator fragments are repacked directly into
// PV A-fragments (m16n8k16 C layout == A layout).
// ---------------------------------------------------------------------------
#define AQ 256
#define AK 64
#define NKT (S_ / AK)        // 32

#define SQ_  0
#define SK0_ (32 * 1024)
#define SK1_ (40 * 1024)
#define SV0_ (48 * 1024)
#define SV1_ (56 * 1024)
#define ASMEM (64 * 1024)

__global__ __launch_bounds__(256, 1)
void attn_mma_f16(const __half* __restrict__ Qg, const __half* __restrict__ Kg,
                  const __half* __restrict__ Vtg, __half* __restrict__ Ctx)
{
    extern __shared__ __align__(128) char sma[];
    const uint32_t sb = smem_u32(sma);
    const int tid = threadIdx.x;
    const int wid = tid >> 5;
    const int lane = tid & 31;
    const int qt = blockIdx.x;   // 0..7
    const int h  = blockIdx.y;
    const int b  = blockIdx.z;

    auto issue_q = [&]() {
#pragma unroll
        for (int i = 0; i < 8; ++i) {
            int idx = tid + 256 * i;
            int row = idx >> 3, c = idx & 7;
            uint32_t dst = sb + SQ_ + sw128((uint32_t)(row * 128 + c * 16));
            const __half* src = Qg + (size_t)((qt * AQ + row) * 2 + b) * E_ + h * DH_ + c * 8;
            CP_ASYNC16(dst, src);
        }
    };
    auto issue_k = [&](uint32_t base, int kt) {
#pragma unroll
        for (int i = 0; i < 2; ++i) {
            int idx = tid + 256 * i;
            int row = idx >> 3, c = idx & 7;
            uint32_t dst = base + sw128((uint32_t)(row * 128 + c * 16));
            const __half* src = Kg + (size_t)((kt * AK + row) * 2 + b) * E_ + h * DH_ + c * 8;
            CP_ASYNC16(dst, src);
        }
    };
    auto issue_v = [&](uint32_t base, int kt) {
#pragma unroll
        for (int i = 0; i < 2; ++i) {
            int idx = tid + 256 * i;
            int row = idx >> 3, c = idx & 7;    // row = d
            uint32_t dst = base + sw128((uint32_t)(row * 128 + c * 16));
            const __half* src = Vtg + ((size_t)(b * H_ + h) * DH_ + row) * S_ + kt * AK + c * 8;
            CP_ASYNC16(dst, src);
        }
    };

    const uint32_t kbuf[2] = { sb + SK0_, sb + SK1_ };
    const uint32_t vbuf[2] = { sb + SV0_, sb + SV1_ };

    issue_q();
    issue_k(kbuf[0], 0);
    issue_v(vbuf[0], 0);
    CP_COMMIT();
    issue_k(kbuf[1], 1);
    issue_v(vbuf[1], 1);
    CP_COMMIT();

    const int a_hi = (lane & 16) ? 1 : 0;
    const int b_row_rel = (lane & 7) + ((lane & 16) >> 1);
    const int b_hi = (lane & 8) ? 1 : 0;
    const int arow[2] = { wid * 32 + (lane & 15), wid * 32 + 16 + (lane & 15) };

    float oc[2][8][4];
#pragma unroll
    for (int mf = 0; mf < 2; ++mf)
#pragma unroll
        for (int n = 0; n < 8; ++n)
#pragma unroll
            for (int r = 0; r < 4; ++r) oc[mf][n][r] = 0.0f;
    float mrow[2][2] = { {-1e30f, -1e30f}, {-1e30f, -1e30f} };
    float lrow[2][2] = { {0.0f, 0.0f}, {0.0f, 0.0f} };

    CP_WAIT1();
    __syncthreads();

    for (int kt = 0; kt < NKT; ++kt) {
        const int buf = kt & 1;

        // ---- S = Q K^T : 2 m-frags x 8 n-frags, k = 64 -> 4 k16 steps
        float sc[2][8][4];
#pragma unroll
        for (int mf = 0; mf < 2; ++mf)
#pragma unroll
            for (int n = 0; n < 8; ++n)
#pragma unroll
                for (int r = 0; r < 4; ++r) sc[mf][n][r] = 0.0f;

#pragma unroll
        for (int s = 0; s < 4; ++s) {
            uint32_t af[2][4];
#pragma unroll
            for (int mf = 0; mf < 2; ++mf) {
                uint32_t off = (uint32_t)(arow[mf] * 128 + (2 * s + a_hi) * 16);
                ldsm_x4(sb + SQ_ + sw128(off), af[mf][0], af[mf][1], af[mf][2], af[mf][3]);
            }
#pragma unroll
            for (int g = 0; g < 4; ++g) {
                int row = g * 16 + b_row_rel;
                uint32_t off = (uint32_t)(row * 128 + (2 * s + b_hi) * 16);
                uint32_t r0, r1, r2, r3;
                ldsm_x4(kbuf[buf] + sw128(off), r0, r1, r2, r3);
                uint32_t bf0[2] = { r0, r1 };
                uint32_t bf1[2] = { r2, r3 };
#pragma unroll
                for (int mf = 0; mf < 2; ++mf) {
                    mma_f16(sc[mf][2 * g + 0], af[mf], bf0);
                    mma_f16(sc[mf][2 * g + 1], af[mf], bf1);
                }
            }
        }

        // ---- online softmax (in-register); sc becomes exp(S - m)
#pragma unroll
        for (int mf = 0; mf < 2; ++mf) {
            float mx0 = -1e30f, mx1 = -1e30f;
#pragma unroll
            for (int n = 0; n < 8; ++n) {
                mx0 = fmaxf(mx0, fmaxf(sc[mf][n][0], sc[mf][n][1]));
                mx1 = fmaxf(mx1, fmaxf(sc[mf][n][2], sc[mf][n][3]));
            }
            mx0 = fmaxf(mx0, __shfl_xor_sync(0xffffffffu, mx0, 1));
            mx0 = fmaxf(mx0, __shfl_xor_sync(0xffffffffu, mx0, 2));
            mx1 = fmaxf(mx1, __shfl_xor_sync(0xffffffffu, mx1, 1));
            mx1 = fmaxf(mx1, __shfl_xor_sync(0xffffffffu, mx1, 2));
            const float mn0 = fmaxf(mrow[mf][0], mx0);
            const float mn1 = fmaxf(mrow[mf][1], mx1);
            const float corr0 = __expf(mrow[mf][0] - mn0);
            const float corr1 = __expf(mrow[mf][1] - mn1);
            mrow[mf][0] = mn0; mrow[mf][1] = mn1;
            float rs0 = 0.0f, rs1 = 0.0f;
#pragma unroll
            for (int n = 0; n < 8; ++n) {
                oc[mf][n][0] *= corr0; oc[mf][n][1] *= corr0;
                oc[mf][n][2] *= corr1; oc[mf][n][3] *= corr1;
                sc[mf][n][0] = __expf(sc[mf][n][0] - mn0);
                sc[mf][n][1] = __expf(sc[mf][n][1] - mn0);
                sc[mf][n][2] = __expf(sc[mf][n][2] - mn1);
                sc[mf][n][3] = __expf(sc[mf][n][3] - mn1);
                rs0 += sc[mf][n][0] + sc[mf][n][1];
                rs1 += sc[mf][n][2] + sc[mf][n][3];
            }
            rs0 += __shfl_xor_sync(0xffffffffu, rs0, 1);
            rs0 += __shfl_xor_sync(0xffffffffu, rs0, 2);
            rs1 += __shfl_xor_sync(0xffffffffu, rs1, 1);
            rs1 += __shfl_xor_sync(0xffffffffu, rs1, 2);
            lrow[mf][0] = lrow[mf][0] * corr0 + rs0;
            lrow[mf][1] = lrow[mf][1] * corr1 + rs1;
        }

        // ---- O += P V : P fragments built in registers from sc
#pragma unroll
        for (int s = 0; s < 4; ++s) {
            uint32_t af[2][4];
#pragma unroll
            for (int mf = 0; mf < 2; ++mf) {
                af[mf][0] = pack_h2(sc[mf][2 * s][0],     sc[mf][2 * s][1]);
                af[mf][1] = pack_h2(sc[mf][2 * s][2],     sc[mf][2 * s][3]);
                af[mf][2] = pack_h2(sc[mf][2 * s + 1][0], sc[mf][2 * s + 1][1]);
                af[mf][3] = pack_h2(sc[mf][2 * s + 1][2], sc[mf][2 * s + 1][3]);
            }
#pragma unroll
            for (int g = 0; g < 4; ++g) {
                int row = g * 16 + b_row_rel;     // row = d (the n dim)
                uint32_t off = (uint32_t)(row * 128 + (2 * s + b_hi) * 16);
                uint32_t r0, r1, r2, r3;
                ldsm_x4(vbuf[buf] + sw128(off), r0, r1, r2, r3);
                uint32_t bf0[2] = { r0, r1 };
                uint32_t bf1[2] = { r2, r3 };
#pragma unroll
                for (int mf = 0; mf < 2; ++mf) {
                    mma_f16(oc[mf][2 * g + 0], af[mf], bf0);
                    mma_f16(oc[mf][2 * g + 1], af[mf], bf1);
                }
            }
        }

        __syncthreads();
        if (kt + 2 < NKT) {
            issue_k(kbuf[buf], kt + 2);
            issue_v(vbuf[buf], kt + 2);
        }
        CP_COMMIT();
        if (kt + 1 < NKT) {
            CP_WAIT1();
            __syncthreads();
        }
    }

    // ---- epilogue: ctx half [(q*B+b)*E + h*64 + col]
    const int tg = lane & 3;
#pragma unroll
    for (int mf = 0; mf < 2; ++mf) {
        const float inv0 = 1.0f / lrow[mf][0];
        const float inv1 = 1.0f / lrow[mf][1];
        const int q0 = qt * AQ + wid * 32 + mf * 16 + (lane >> 2);
#pragma unroll
        for (int n = 0; n < 8; ++n) {
            const int col = h * DH_ + n * 8 + 2 * tg;
            uint32_t lo = pack_h2(oc[mf][n][0] * inv0, oc[mf][n][1] * inv0);
            uint32_t hi = pack_h2(oc[mf][n][2] * inv1, oc[mf][n][3] * inv1);
            *(uint32_t*)(Ctx + (size_t)(q0 * 2 + b) * E_ + col) = lo;
            *(uint32_t*)(Ctx + (size_t)((q0 + 8) * 2 + b) * E_ + col) = hi;
        }
    }
}

// ---------------------------------------------------------------------------
// Launcher
// ---------------------------------------------------------------------------
extern "C" void kernel_launch(void* const* d_in, const int* in_sizes, int n_in,
                              void* d_out, int out_size)
{
    const float* query = (const float*)d_in[0];
    const float* wq = (const float*)d_in[1];
    const float* bq = (const float*)d_in[2];
    const float* wk = (const float*)d_in[3];
    const float* bk = (const float*)d_in[4];
    const float* wv = (const float*)d_in[5];
    const float* bv = (const float*)d_in[6];
    const float* wo = (const float*)d_in[7];
    const float* bo = (const float*)d_in[8];
    float* out = (float*)d_out;

    __half *hx, *hwq, *hwk, *hwv, *hwo, *qb, *kb, *vtb, *cb;
    cudaGetSymbolAddress((void**)&hx,  g_hx);
    cudaGetSymbolAddress((void**)&hwq, g_hwq);
    cudaGetSymbolAddress((void**)&hwk, g_hwk);
    cudaGetSymbolAddress((void**)&hwv, g_hwv);
    cudaGetSymbolAddress((void**)&hwo, g_hwo);
    cudaGetSymbolAddress((void**)&qb,  g_q);
    cudaGetSymbolAddress((void**)&kb,  g_k);
    cudaGetSymbolAddress((void**)&vtb, g_vt);
    cudaGetSymbolAddress((void**)&cb,  g_ctx);

    const int nq4 = M_ * E_ / 4;     // 1M
    const int nw4 = E_ * E_ / 4;     // 256K
    cvt_f32_f16<<<(nq4 + 255) / 256, 256>>>(query, hx, nq4);
    cvt_f32_f16<<<(nw4 + 255) / 256, 256>>>(wq, hwq, nw4);
    cvt_f32_f16<<<(nw4 + 255) / 256, 256>>>(wk, hwk, nw4);
    cvt_f32_f16<<<(nw4 + 255) / 256, 256>>>(wv, hwv, nw4);
    cvt_f32_f16<<<(nw4 + 255) / 256, 256>>>(wo, hwo, nw4);

    cudaFuncSetAttribute(gemm_mma_f16, cudaFuncAttributeMaxDynamicSharedMemorySize, GEMM_SMEM);
    cudaFuncSetAttribute(attn_mma_f16, cudaFuncAttributeMaxDynamicSharedMemorySize, ASMEM);

    dim3 ggrid(E_ / 128, M_ / 128);   // (8, 32)

    gemm_mma_f16<<<ggrid, 256, GEMM_SMEM>>>(hx, hwq, bq, qb,  SCALING_, 1);
    gemm_mma_f16<<<ggrid, 256, GEMM_SMEM>>>(hx, hwk, bk, kb,  1.0f,     1);
    gemm_mma_f16<<<ggrid, 256, GEMM_SMEM>>>(hx, hwv, bv, vtb, 1.0f,     2);

    attn_mma_f16<<<dim3(S_ / AQ, H_, B_), 256, ASMEM>>>(qb, kb, vtb, cb);

    gemm_mma_f16<<<ggrid, 256, GEMM_SMEM>>>(cb, hwo, bo, out, 1.0f,     0);
}

// round 7
// speedup vs baseline: 8.3807x; 1.0870x over previous
#include <cuda_runtime.h>
#include <cuda_fp16.h>
#include <cstdint>

// Problem dims (fixed by the reference)
#define S_ 2048
#define B_ 2
#define E_ 1024
#define H_ 16
#define DH_ 64
#define M_ (S_ * B_)
#define SCALING_ 0.125f
#define LOG2E_ 1.4426950408889634f

// ---------------------------------------------------------------------------
// Scratch (allocation-free rule: __device__ globals), all fp16
// ---------------------------------------------------------------------------
__device__ __half g_hx[(size_t)M_ * E_];     // query in fp16
__device__ __half g_hwq[(size_t)E_ * E_];
__device__ __half g_hwk[(size_t)E_ * E_];
__device__ __half g_hwv[(size_t)E_ * E_];
__device__ __half g_hwo[(size_t)E_ * E_];
__device__ __half g_q[(size_t)M_ * E_];      // holds log2e-prescaled Q
__device__ __half g_k[(size_t)M_ * E_];
__device__ __half g_vt[(size_t)M_ * E_];     // V transposed: [b][h][d][s]
__device__ __half g_ctx[(size_t)M_ * E_];

// ---------------------------------------------------------------------------
// Helpers (.target sm_103 safe)
// ---------------------------------------------------------------------------
__device__ __forceinline__ uint32_t smem_u32(const void* p) {
    uint32_t a;
    asm("{ .reg .u64 t; cvta.to.shared.u64 t, %1; cvt.u32.u64 %0, t; }"
        : "=r"(a) : "l"(p));
    return a;
}

__device__ __forceinline__ uint32_t pack_h2(float a, float b) {
    __half2 h = __floats2half2_rn(a, b);
    return *reinterpret_cast<uint32_t*>(&h);
}

__device__ __forceinline__ void ldsm_x4(uint32_t addr, uint32_t& r0, uint32_t& r1,
                                        uint32_t& r2, uint32_t& r3) {
    asm volatile("ldmatrix.sync.aligned.m8n8.x4.shared.b16 {%0,%1,%2,%3}, [%4];"
                 : "=r"(r0), "=r"(r1), "=r"(r2), "=r"(r3) : "r"(addr));
}

__device__ __forceinline__ void mma_f16(float* d, const uint32_t* a, const uint32_t* b) {
    asm volatile(
        "mma.sync.aligned.m16n8k16.row.col.f32.f16.f16.f32 "
        "{%0,%1,%2,%3}, {%4,%5,%6,%7}, {%8,%9}, {%0,%1,%2,%3};"
        : "+f"(d[0]), "+f"(d[1]), "+f"(d[2]), "+f"(d[3])
        : "r"(a[0]), "r"(a[1]), "r"(a[2]), "r"(a[3]), "r"(b[0]), "r"(b[1]));
}

#define CP_ASYNC16(dst, src) \
    asm volatile("cp.async.cg.shared.global [%0], [%1], 16;" \
                 :: "r"(dst), "l"(src) : "memory")
#define CP_COMMIT() asm volatile("cp.async.commit_group;" ::: "memory")
#define CP_WAIT1()  asm volatile("cp.async.wait_group 1;" ::: "memory")
#define CP_WAIT0()  asm volatile("cp.async.wait_group 0;" ::: "memory")

__device__ __forceinline__ uint32_t sw128(uint32_t off) {
    return off ^ ((off >> 3) & 0x70);
}

// ---------------------------------------------------------------------------
// Batched fp32 -> fp16 convert: x (1M float4) then 4 weights (256K float4 each)
// ---------------------------------------------------------------------------
#define XN4 (M_ * E_ / 4)        // 1048576
#define WN4 (E_ * E_ / 4)        // 262144

__global__ __launch_bounds__(256)
void cvt_all_f16(const float* __restrict__ x,
                 const float* __restrict__ w0, const float* __restrict__ w1,
                 const float* __restrict__ w2, const float* __restrict__ w3,
                 __half* __restrict__ hx,
                 __half* __restrict__ h0, __half* __restrict__ h1,
                 __half* __restrict__ h2, __half* __restrict__ h3)
{
    int i = blockIdx.x * blockDim.x + threadIdx.x;
    const float* src;
    __half* dst;
    int j;
    if (i < XN4)                { src = x;  dst = hx; j = i; }
    else if (i < XN4 + WN4)     { src = w0; dst = h0; j = i - XN4; }
    else if (i < XN4 + 2 * WN4) { src = w1; dst = h1; j = i - XN4 - WN4; }
    else if (i < XN4 + 3 * WN4) { src = w2; dst = h2; j = i - XN4 - 2 * WN4; }
    else                        { src = w3; dst = h3; j = i - XN4 - 3 * WN4; }
    float4 v = ((const float4*)src)[j];
    uint2 o;
    o.x = pack_h2(v.x, v.y);
    o.y = pack_h2(v.z, v.w);
    ((uint2*)dst)[j] = o;
}

// ---------------------------------------------------------------------------
// fp16 mma GEMM (NT): C[m][n] = alpha*(sum_k A[m][k]*W[n][k] + bias[n])
// fused QKV variant: blockIdx.z selects {W, bias, C, alpha, mode}.
// mode 0: fp32 out; 1: half out; 2: half transposed out [b][h][d][s].
// ---------------------------------------------------------------------------
#define GK 1024
#define BKH 64
#define NCH (GK / BKH)            // 16
#define OPB (128 * 128)           // 16 KB per operand per buffer
#define GEMM_SMEM 69632

__device__ __forceinline__
void gemm_body(const __half* __restrict__ A, const __half* __restrict__ W,
               const float* __restrict__ bias, void* __restrict__ Cout,
               float alpha, int mode, char* smg, int bx, int by)
{
    const uint32_t sb = smem_u32(smg);
    const uint32_t aB[2] = { sb, sb + 2 * OPB };
    const uint32_t bB[2] = { sb + OPB, sb + 3 * OPB };

    const int tid = threadIdx.x;
    const int wid = tid >> 5;
    const int lane = tid & 31;
    const int warp_m = wid & 1;
    const int warp_n = wid >> 1;

    const __half* Ap = A + (size_t)(by * 128) * GK;
    const __half* Wp = W + (size_t)(bx * 128) * GK;

    const int ldrow = tid >> 3;
    const int ldc16 = tid & 7;

    const int a_hi = (lane & 16) ? 1 : 0;
    const int b_row_rel = (lane & 7) + ((lane & 16) >> 1);
    const int b_hi = (lane & 8) ? 1 : 0;

    float acc[4][4][4];
#pragma unroll
    for (int i = 0; i < 4; ++i)
#pragma unroll
        for (int j = 0; j < 4; ++j)
#pragma unroll
            for (int r = 0; r < 4; ++r) acc[i][j][r] = 0.0f;

    auto issue = [&](int c, int buf) {
#pragma unroll
        for (int i = 0; i < 4; ++i) {
            int row = ldrow + i * 32;
            uint32_t sw = sw128((uint32_t)(row * 128 + ldc16 * 16));
            const __half* ga = Ap + (size_t)row * GK + c * BKH + ldc16 * 8;
            const __half* gw = Wp + (size_t)row * GK + c * BKH + ldc16 * 8;
            CP_ASYNC16(aB[buf] + sw, ga);
            CP_ASYNC16(bB[buf] + sw, gw);
        }
    };

    issue(0, 0); CP_COMMIT();
    issue(1, 1); CP_COMMIT();

    for (int c = 0; c < NCH; ++c) {
        const int buf = c & 1;
        CP_WAIT1();
        __syncthreads();

#pragma unroll
        for (int s = 0; s < 4; ++s) {
            uint32_t bfr[4][2];
#pragma unroll
            for (int nfp = 0; nfp < 2; ++nfp) {
                int row = warp_n * 32 + nfp * 16 + b_row_rel;
                uint32_t off = (uint32_t)(row * 128 + (2 * s + b_hi) * 16);
                uint32_t r0, r1, r2, r3;
                ldsm_x4(bB[buf] + sw128(off), r0, r1, r2, r3);
                bfr[2 * nfp + 0][0] = r0; bfr[2 * nfp + 0][1] = r1;
                bfr[2 * nfp + 1][0] = r2; bfr[2 * nfp + 1][1] = r3;
            }
#pragma unroll
            for (int mf = 0; mf < 4; ++mf) {
                int row = warp_m * 64 + mf * 16 + (lane & 15);
                uint32_t off = (uint32_t)(row * 128 + (2 * s + a_hi) * 16);
                uint32_t af[4];
                ldsm_x4(aB[buf] + sw128(off), af[0], af[1], af[2], af[3]);
#pragma unroll
                for (int nf = 0; nf < 4; ++nf)
                    mma_f16(acc[mf][nf], af, bfr[nf]);
            }
        }
        __syncthreads();
        if (c + 2 < NCH) issue(c + 2, buf);
        CP_COMMIT();
    }

    const int gq = lane >> 2;
    const int tg = lane & 3;

    if (mode == 0) {
        float* C = (float*)Cout;
#pragma unroll
        for (int nf = 0; nf < 4; ++nf) {
            const int col = bx * 128 + warp_n * 32 + nf * 8 + 2 * tg;
            const float bv0 = bias[col], bv1 = bias[col + 1];
#pragma unroll
            for (int mf = 0; mf < 4; ++mf) {
                const int r0 = by * 128 + warp_m * 64 + mf * 16 + gq;
                float2 lo, hi;
                lo.x = alpha * (acc[mf][nf][0] + bv0);
                lo.y = alpha * (acc[mf][nf][1] + bv1);
                hi.x = alpha * (acc[mf][nf][2] + bv0);
                hi.y = alpha * (acc[mf][nf][3] + bv1);
                *(float2*)(C + (size_t)r0 * E_ + col) = lo;
                *(float2*)(C + (size_t)(r0 + 8) * E_ + col) = hi;
            }
        }
        return;
    }
    if (mode == 1) {
        __half* C = (__half*)Cout;
#pragma unroll
        for (int nf = 0; nf < 4; ++nf) {
            const int col = bx * 128 + warp_n * 32 + nf * 8 + 2 * tg;
            const float bv0 = bias[col], bv1 = bias[col + 1];
#pragma unroll
            for (int mf = 0; mf < 4; ++mf) {
                const int r0 = by * 128 + warp_m * 64 + mf * 16 + gq;
                uint32_t lo = pack_h2(alpha * (acc[mf][nf][0] + bv0),
                                      alpha * (acc[mf][nf][1] + bv1));
                uint32_t hi = pack_h2(alpha * (acc[mf][nf][2] + bv0),
                                      alpha * (acc[mf][nf][3] + bv1));
                *(uint32_t*)(C + (size_t)r0 * E_ + col) = lo;
                *(uint32_t*)(C + (size_t)(r0 + 8) * E_ + col) = hi;
            }
        }
        return;
    }

    // mode 2: transposed epilogue -> Cvt[b][h][d][s] as half
    CP_WAIT0();
    __syncthreads();
    float* Cs = (float*)smg;     // [128][132]
#pragma unroll
    for (int nf = 0; nf < 4; ++nf) {
        const int colL = warp_n * 32 + nf * 8 + 2 * tg;
        const int colG = bx * 128 + colL;
        const float bv0 = bias[colG], bv1 = bias[colG + 1];
#pragma unroll
        for (int mf = 0; mf < 4; ++mf) {
            const int r0 = warp_m * 64 + mf * 16 + gq;
            Cs[r0 * 132 + colL]           = acc[mf][nf][0] + bv0;
            Cs[r0 * 132 + colL + 1]       = acc[mf][nf][1] + bv1;
            Cs[(r0 + 8) * 132 + colL]     = acc[mf][nf][2] + bv0;
            Cs[(r0 + 8) * 132 + colL + 1] = acc[mf][nf][3] + bv1;
        }
    }
    __syncthreads();
    {
        __half* C = (__half*)Cout;
        const int col = tid >> 1;
        const int b = tid & 1;
        const int h = bx * 2 + (col >> 6);
        const int d = col & 63;
        __half* dst = C + ((size_t)(b * H_ + h) * DH_ + d) * S_ + by * 64;
#pragma unroll
        for (int j = 0; j < 16; ++j) {
            uint2 o;
            o.x = pack_h2(Cs[((4 * j + 0) * 2 + b) * 132 + col],
                          Cs[((4 * j + 1) * 2 + b) * 132 + col]);
            o.y = pack_h2(Cs[((4 * j + 2) * 2 + b) * 132 + col],
                          Cs[((4 * j + 3) * 2 + b) * 132 + col]);
            *(uint2*)(dst + 4 * j) = o;
        }
    }
}

// fused QKV: z = 0 -> Q (alpha = SCALING*LOG2E, half out), 1 -> K, 2 -> Vt
__global__ __launch_bounds__(256, 2)
void gemm_qkv_f16(const __half* __restrict__ A,
                  const __half* __restrict__ Wq, const __half* __restrict__ Wk,
                  const __half* __restrict__ Wv,
                  const float* __restrict__ bq, const float* __restrict__ bk,
                  const float* __restrict__ bv,
                  __half* __restrict__ Q, __half* __restrict__ K,
                  __half* __restrict__ Vt)
{
    extern __shared__ __align__(128) char smg[];
    const int z = blockIdx.z;
    const __half* W = (z == 0) ? Wq : (z == 1) ? Wk : Wv;
    const float* bias = (z == 0) ? bq : (z == 1) ? bk : bv;
    void* C = (z == 0) ? (void*)Q : (z == 1) ? (void*)K : (void*)Vt;
    const float alpha = (z == 0) ? SCALING_ * LOG2E_ : 1.0f;
    const int mode = (z == 2) ? 2 : 1;
    gemm_body(A, W, bias, C, alpha, mode, smg, blockIdx.x, blockIdx.y);
}

// single GEMM (output projection)
__global__ __launch_bounds__(256, 2)
void gemm_out_f16(const __half* __restrict__ A, const __half* __restrict__ W,
                  const float* __restrict__ bias, float* __restrict__ C)
{
    extern __shared__ __align__(128) char smg[];
    gemm_body(A, W, bias, C, 1.0f, 0, smg, blockIdx.x, blockIdx.y);
}

// ---------------------------------------------------------------------------
// fp16 tensor-core flash attention (exp2 domain: Q pre-scaled by log2e).
// CTA = (q-tile 256, head, batch); 8 warps x 32 q-rows; K-tiles of 64,
// cp.async double buffered. P stays in registers.
// ---------------------------------------------------------------------------
#define AQ 256
#define AK 64
#define NKT (S_ / AK)        // 32

#define SQ_  0
#define SK0_ (32 * 1024)
#define SK1_ (40 * 1024)
#define SV0_ (48 * 1024)
#define SV1_ (56 * 1024)
#define ASMEM (64 * 1024)

__global__ __launch_bounds__(256, 1)
void attn_mma_f16(const __half* __restrict__ Qg, const __half* __restrict__ Kg,
                  const __half* __restrict__ Vtg, __half* __restrict__ Ctx)
{
    extern __shared__ __align__(128) char sma[];
    const uint32_t sb = smem_u32(sma);
    const int tid = threadIdx.x;
    const int wid = tid >> 5;
    const int lane = tid & 31;
    const int qt = blockIdx.x;
    const int h  = blockIdx.y;
    const int b  = blockIdx.z;

    auto issue_q = [&]() {
#pragma unroll
        for (int i = 0; i < 8; ++i) {
            int idx = tid + 256 * i;
            int row = idx >> 3, c = idx & 7;
            uint32_t dst = sb + SQ_ + sw128((uint32_t)(row * 128 + c * 16));
            const __half* src = Qg + (size_t)((qt * AQ + row) * 2 + b) * E_ + h * DH_ + c * 8;
            CP_ASYNC16(dst, src);
        }
    };
    auto issue_k = [&](uint32_t base, int kt) {
#pragma unroll
        for (int i = 0; i < 2; ++i) {
            int idx = tid + 256 * i;
            int row = idx >> 3, c = idx & 7;
            uint32_t dst = base + sw128((uint32_t)(row * 128 + c * 16));
            const __half* src = Kg + (size_t)((kt * AK + row) * 2 + b) * E_ + h * DH_ + c * 8;
            CP_ASYNC16(dst, src);
        }
    };
    auto issue_v = [&](uint32_t base, int kt) {
#pragma unroll
        for (int i = 0; i < 2; ++i) {
            int idx = tid + 256 * i;
            int row = idx >> 3, c = idx & 7;
            uint32_t dst = base + sw128((uint32_t)(row * 128 + c * 16));
            const __half* src = Vtg + ((size_t)(b * H_ + h) * DH_ + row) * S_ + kt * AK + c * 8;
            CP_ASYNC16(dst, src);
        }
    };

    const uint32_t kbuf[2] = { sb + SK0_, sb + SK1_ };
    const uint32_t vbuf[2] = { sb + SV0_, sb + SV1_ };

    issue_q();
    issue_k(kbuf[0], 0);
    issue_v(vbuf[0], 0);
    CP_COMMIT();
    issue_k(kbuf[1], 1);
    issue_v(vbuf[1], 1);
    CP_COMMIT();

    const int a_hi = (lane & 16) ? 1 : 0;
    const int b_row_rel = (lane & 7) + ((lane & 16) >> 1);
    const int b_hi = (lane & 8) ? 1 : 0;
    const int arow[2] = { wid * 32 + (lane & 15), wid * 32 + 16 + (lane & 15) };

    float oc[2][8][4];
#pragma unroll
    for (int mf = 0; mf < 2; ++mf)
#pragma unroll
        for (int n = 0; n < 8; ++n)
#pragma unroll
            for (int r = 0; r < 4; ++r) oc[mf][n][r] = 0.0f;
    float mrow[2][2] = { {-1e30f, -1e30f}, {-1e30f, -1e30f} };
    float lrow[2][2] = { {0.0f, 0.0f}, {0.0f, 0.0f} };

    CP_WAIT1();
    __syncthreads();

    for (int kt = 0; kt < NKT; ++kt) {
        const int buf = kt & 1;

        // ---- S' = (log2e * Q) K^T
        float sc[2][8][4];
#pragma unroll
        for (int mf = 0; mf < 2; ++mf)
#pragma unroll
            for (int n = 0; n < 8; ++n)
#pragma unroll
                for (int r = 0; r < 4; ++r) sc[mf][n][r] = 0.0f;

#pragma unroll
        for (int s = 0; s < 4; ++s) {
            uint32_t af[2][4];
#pragma unroll
            for (int mf = 0; mf < 2; ++mf) {
                uint32_t off = (uint32_t)(arow[mf] * 128 + (2 * s + a_hi) * 16);
                ldsm_x4(sb + SQ_ + sw128(off), af[mf][0], af[mf][1], af[mf][2], af[mf][3]);
            }
#pragma unroll
            for (int g = 0; g < 4; ++g) {
                int row = g * 16 + b_row_rel;
                uint32_t off = (uint32_t)(row * 128 + (2 * s + b_hi) * 16);
                uint32_t r0, r1, r2, r3;
                ldsm_x4(kbuf[buf] + sw128(off), r0, r1, r2, r3);
                uint32_t bf0[2] = { r0, r1 };
                uint32_t bf1[2] = { r2, r3 };
#pragma unroll
                for (int mf = 0; mf < 2; ++mf) {
                    mma_f16(sc[mf][2 * g + 0], af[mf], bf0);
                    mma_f16(sc[mf][2 * g + 1], af[mf], bf1);
                }
            }
        }

        // ---- online softmax in exp2 domain; sc becomes 2^(S' - m')
#pragma unroll
        for (int mf = 0; mf < 2; ++mf) {
            float mx0 = -1e30f, mx1 = -1e30f;
#pragma unroll
            for (int n = 0; n < 8; ++n) {
                mx0 = fmaxf(mx0, fmaxf(sc[mf][n][0], sc[mf][n][1]));
                mx1 = fmaxf(mx1, fmaxf(sc[mf][n][2], sc[mf][n][3]));
            }
            mx0 = fmaxf(mx0, __shfl_xor_sync(0xffffffffu, mx0, 1));
            mx0 = fmaxf(mx0, __shfl_xor_sync(0xffffffffu, mx0, 2));
            mx1 = fmaxf(mx1, __shfl_xor_sync(0xffffffffu, mx1, 1));
            mx1 = fmaxf(mx1, __shfl_xor_sync(0xffffffffu, mx1, 2));
            const float mn0 = fmaxf(mrow[mf][0], mx0);
            const float mn1 = fmaxf(mrow[mf][1], mx1);
            const float corr0 = exp2f(mrow[mf][0] - mn0);
            const float corr1 = exp2f(mrow[mf][1] - mn1);
            mrow[mf][0] = mn0; mrow[mf][1] = mn1;
            float rs0 = 0.0f, rs1 = 0.0f;
#pragma unroll
            for (int n = 0; n < 8; ++n) {
                oc[mf][n][0] *= corr0; oc[mf][n][1] *= corr0;
                oc[mf][n][2] *= corr1; oc[mf][n][3] *= corr1;
                sc[mf][n][0] = exp2f(sc[mf][n][0] - mn0);
                sc[mf][n][1] = exp2f(sc[mf][n][1] - mn0);
                sc[mf][n][2] = exp2f(sc[mf][n][2] - mn1);
                sc[mf][n][3] = exp2f(sc[mf][n][3] - mn1);
                rs0 += sc[mf][n][0] + sc[mf][n][1];
                rs1 += sc[mf][n][2] + sc[mf][n][3];
            }
            rs0 += __shfl_xor_sync(0xffffffffu, rs0, 1);
            rs0 += __shfl_xor_sync(0xffffffffu, rs0, 2);
            rs1 += __shfl_xor_sync(0xffffffffu, rs1, 1);
            rs1 += __shfl_xor_sync(0xffffffffu, rs1, 2);
            lrow[mf][0] = lrow[mf][0] * corr0 + rs0;
            lrow[mf][1] = lrow[mf][1] * corr1 + rs1;
        }

        // ---- O += P V : P fragments built in registers from sc
#pragma unroll
        for (int s = 0; s < 4; ++s) {
            uint32_t af[2][4];
#pragma unroll
            for (int mf = 0; mf < 2; ++mf) {
                af[mf][0] = pack_h2(sc[mf][2 * s][0],     sc[mf][2 * s][1]);
                af[mf][1] = pack_h2(sc[mf][2 * s][2],     sc[mf][2 * s][3]);
                af[mf][2] = pack_h2(sc[mf][2 * s + 1][0], sc[mf][2 * s + 1][1]);
                af[mf][3] = pack_h2(sc[mf][2 * s + 1][2], sc[mf][2 * s + 1][3]);
            }
#pragma unroll
            for (int g = 0; g < 4; ++g) {
                int row = g * 16 + b_row_rel;
                uint32_t off = (uint32_t)(row * 128 + (2 * s + b_hi) * 16);
                uint32_t r0, r1, r2, r3;
                ldsm_x4(vbuf[buf] + sw128(off), r0, r1, r2, r3);
                uint32_t bf0[2] = { r0, r1 };
                uint32_t bf1[2] = { r2, r3 };
#pragma unroll
                for (int mf = 0; mf < 2; ++mf) {
                    mma_f16(oc[mf][2 * g + 0], af[mf], bf0);
                    mma_f16(oc[mf][2 * g + 1], af[mf], bf1);
                }
            }
        }

        __syncthreads();
        if (kt + 2 < NKT) {
            issue_k(kbuf[buf], kt + 2);
            issue_v(vbuf[buf], kt + 2);
        }
        CP_COMMIT();
        if (kt + 1 < NKT) {
            CP_WAIT1();
            __syncthreads();
        }
    }

    // ---- epilogue
    const int tg = lane & 3;
#pragma unroll
    for (int mf = 0; mf < 2; ++mf) {
        const float inv0 = 1.0f / lrow[mf][0];
        const float inv1 = 1.0f / lrow[mf][1];
        const int q0 = qt * AQ + wid * 32 + mf * 16 + (lane >> 2);
#pragma unroll
        for (int n = 0; n < 8; ++n) {
            const int col = h * DH_ + n * 8 + 2 * tg;
            uint32_t lo = pack_h2(oc[mf][n][0] * inv0, oc[mf][n][1] * inv0);
            uint32_t hi = pack_h2(oc[mf][n][2] * inv1, oc[mf][n][3] * inv1);
            *(uint32_t*)(Ctx + (size_t)(q0 * 2 + b) * E_ + col) = lo;
            *(uint32_t*)(Ctx + (size_t)((q0 + 8) * 2 + b) * E_ + col) = hi;
        }
    }
}

// ---------------------------------------------------------------------------
// Launcher (4 launches total)
// ---------------------------------------------------------------------------
extern "C" void kernel_launch(void* const* d_in, const int* in_sizes, int n_in,
                              void* d_out, int out_size)
{
    const float* query = (const float*)d_in[0];
    const float* wq = (const float*)d_in[1];
    const float* bq = (const float*)d_in[2];
    const float* wk = (const float*)d_in[3];
    const float* bk = (const float*)d_in[4];
    const float* wv = (const float*)d_in[5];
    const float* bv = (const float*)d_in[6];
    const float* wo = (const float*)d_in[7];
    const float* bo = (const float*)d_in[8];
    float* out = (float*)d_out;

    __half *hx, *hwq, *hwk, *hwv, *hwo, *qb, *kb, *vtb, *cb;
    cudaGetSymbolAddress((void**)&hx,  g_hx);
    cudaGetSymbolAddress((void**)&hwq, g_hwq);
    cudaGetSymbolAddress((void**)&hwk, g_hwk);
    cudaGetSymbolAddress((void**)&hwv, g_hwv);
    cudaGetSymbolAddress((void**)&hwo, g_hwo);
    cudaGetSymbolAddress((void**)&qb,  g_q);
    cudaGetSymbolAddress((void**)&kb,  g_k);
    cudaGetSymbolAddress((void**)&vtb, g_vt);
    cudaGetSymbolAddress((void**)&cb,  g_ctx);

    const int ntot4 = XN4 + 4 * WN4;     // 2097152
    cvt_all_f16<<<(ntot4 + 255) / 256, 256>>>(query, wq, wk, wv, wo,
                                              hx, hwq, hwk, hwv, hwo);

    cudaFuncSetAttribute(gemm_qkv_f16, cudaFuncAttributeMaxDynamicSharedMemorySize, GEMM_SMEM);
    cudaFuncSetAttribute(gemm_out_f16, cudaFuncAttributeMaxDynamicSharedMemorySize, GEMM_SMEM);
    cudaFuncSetAttribute(attn_mma_f16, cudaFuncAttributeMaxDynamicSharedMemorySize, ASMEM);

    gemm_qkv_f16<<<dim3(E_ / 128, M_ / 128, 3), 256, GEMM_SMEM>>>(
        hx, hwq, hwk, hwv, bq, bk, bv, qb, kb, vtb);

    attn_mma_f16<<<dim3(S_ / AQ, H_, B_), 256, ASMEM>>>(qb, kb, vtb, cb);

    gemm_out_f16<<<dim3(E_ / 128, M_ / 128), 256, GEMM_SMEM>>>(cb, hwo, bo, out);
}